// round 5
// baseline (speedup 1.0000x reference)
#include <cuda_runtime.h>
#include <cstdint>
#include <cstddef>

// Problem constants (fixed by setup_inputs)
#define DIMSZ   1024
#define HD      64
#define NHEADS  16
#define BL      4096            // B*L
#define MROWS   2048
#define QT      128             // queries per attention CTA
#define MC      64              // memory rows per chunk
#define NCH     (MROWS / MC)    // 32
// BETA * log2(e): softmax in base 2 (single EX2 per element)
#define SCALE_LOG2 23.083120654223414f

typedef unsigned long long ull;

// ping-pong scratch (no allocations allowed)
__device__ float g_bufA[(size_t)BL * DIMSZ];
__device__ float g_bufB[(size_t)BL * DIMSZ];

// ---------------- packed f32x2 helpers ----------------
__device__ __forceinline__ ull pack2(float lo, float hi) {
    ull r; asm("mov.b64 %0, {%1, %2};" : "=l"(r) : "f"(lo), "f"(hi)); return r;
}
__device__ __forceinline__ void unpack2(ull v, float& lo, float& hi) {
    asm("mov.b64 {%0, %1}, %2;" : "=f"(lo), "=f"(hi) : "l"(v));
}
__device__ __forceinline__ void ffma2(ull& d, ull a, ull b) {
    asm("fma.rn.f32x2 %0, %1, %2, %0;" : "+l"(d) : "l"(a), "l"(b));
}
__device__ __forceinline__ ull mul2(ull a, ull b) {
    ull r; asm("mul.rn.f32x2 %0, %1, %2;" : "=l"(r) : "l"(a), "l"(b)); return r;
}
__device__ __forceinline__ float ex2(float x) {
    float r; asm("ex2.approx.f32 %0, %1;" : "=f"(r) : "f"(x)); return r;
}

// =======================================================================
// Dense linear: C[4096][1024] = A @ W^T + bias   (torch Linear, W=[out,in])
// EXACT Round-2 version (measured 236 us): tile 128x128, kt=16, 256 thr,
// 8x8 micro via f32x2.
// =======================================================================
__global__ void __launch_bounds__(256, 2)
linear_kernel(float* __restrict__ C, const float* __restrict__ A,
              const float* __restrict__ W, const float* __restrict__ bias)
{
    __shared__ float As[16][132];   // As[k][i]
    __shared__ float Bs[16][132];   // Bs[k][j]
    const int tid = threadIdx.x;
    const int tx  = tid & 15;       // j-tile
    const int ty  = tid >> 4;       // i-tile
    const int i0  = blockIdx.y * 128;
    const int j0  = blockIdx.x * 128;

    ull acc[8][4];
    {
        const float* bp = bias + j0 + tx * 8;
        float4 b0 = *(const float4*)bp;
        float4 b1 = *(const float4*)(bp + 4);
        ull p0 = pack2(b0.x, b0.y), p1 = pack2(b0.z, b0.w);
        ull p2 = pack2(b1.x, b1.y), p3 = pack2(b1.z, b1.w);
        #pragma unroll
        for (int ii = 0; ii < 8; ii++) {
            acc[ii][0] = p0; acc[ii][1] = p1; acc[ii][2] = p2; acc[ii][3] = p3;
        }
    }

    const int lk = tid & 15;        // k within tile
    const int ib = tid >> 4;        // base row

    for (int kt = 0; kt < 64; kt++) {
        __syncthreads();
        const float* Ag = A + (size_t)(i0 + ib) * DIMSZ + kt * 16 + lk;
        const float* Wg = W + (size_t)(j0 + ib) * DIMSZ + kt * 16 + lk;
        #pragma unroll
        for (int rep = 0; rep < 8; rep++) {
            As[lk][ib + rep * 16] = Ag[(size_t)rep * 16 * DIMSZ];
            Bs[lk][ib + rep * 16] = Wg[(size_t)rep * 16 * DIMSZ];
        }
        __syncthreads();
        #pragma unroll
        for (int k = 0; k < 16; k++) {
            const float* ap = &As[k][ty * 8];
            float4 a0 = *(const float4*)ap;
            float4 a1 = *(const float4*)(ap + 4);
            const float* bp = &Bs[k][tx * 8];
            ulonglong2 w0 = *(const ulonglong2*)bp;
            ulonglong2 w1 = *(const ulonglong2*)(bp + 4);
            float a[8] = {a0.x, a0.y, a0.z, a0.w, a1.x, a1.y, a1.z, a1.w};
            #pragma unroll
            for (int ii = 0; ii < 8; ii++) {
                ull ad = pack2(a[ii], a[ii]);
                ffma2(acc[ii][0], ad, w0.x);
                ffma2(acc[ii][1], ad, w0.y);
                ffma2(acc[ii][2], ad, w1.x);
                ffma2(acc[ii][3], ad, w1.y);
            }
        }
    }

    #pragma unroll
    for (int ii = 0; ii < 8; ii++) {
        float4 o0, o1;
        unpack2(acc[ii][0], o0.x, o0.y);
        unpack2(acc[ii][1], o0.z, o0.w);
        unpack2(acc[ii][2], o1.x, o1.y);
        unpack2(acc[ii][3], o1.z, o1.w);
        float* cp = C + (size_t)(i0 + ty * 8 + ii) * DIMSZ + j0 + tx * 8;
        *(float4*)cp       = o0;
        *(float4*)(cp + 4) = o1;
    }
}

// =======================================================================
// Fused Hopfield retrieval (one iteration):
//   dst[r, h*64+d] = sum_m softmax_m(16 * q . mem[m]) * mem[m, d]
// CTA: 128 query rows x 1 head, 256 threads, 2 CTAs/SM (smem ~105 KB).
// Flash-style online softmax over 32 chunks of 64 memory rows.
// S micro: 4q x 8m (pairs along m). PV micro: 4q x 8d (pairs along d).
// =======================================================================
// dynamic smem layout (floats):
#define SM_QTS   0                          // Qts[64][132] (transposed, scaled)
#define SM_KTS   (64 * 132)                 // Kts[64][68]  (transposed K chunk)
#define SM_VS    (SM_KTS + 64 * 68)         // Vs[64][68]   (straight V chunk)
#define SM_PS    (SM_VS + 64 * 68)          // Ps[128][68]
#define SM_ALPHA (SM_PS + 128 * 68)         // [128]
#define SM_MAXR  (SM_ALPHA + 128)           // [128]
#define SM_LSUM  (SM_MAXR + 128)            // [128]
#define SM_FLOATS (SM_LSUM + 128)
#define SM_BYTES  (SM_FLOATS * 4)           // 104,960 B -> 2 CTAs/SM

__global__ void __launch_bounds__(256, 2)
hopfield_attn_kernel(float* __restrict__ dst, const float* __restrict__ src,
                     const float* __restrict__ mem)
{
    extern __shared__ float sm[];
    float* Qts    = sm + SM_QTS;
    float* Kts    = sm + SM_KTS;
    float* Vs     = sm + SM_VS;
    float* Ps     = sm + SM_PS;
    float* rAlpha = sm + SM_ALPHA;
    float* rMax   = sm + SM_MAXR;
    float* rLsum  = sm + SM_LSUM;

    const int tid = threadIdx.x;
    const int h   = blockIdx.y;
    const int r0  = blockIdx.x * QT;

    // ---- load Q (scaled), transposed Qts[d][i] ----
    {
        const int i = tid & 127, seg = tid >> 7;   // seg 0/1 -> 32 d each
        const float* gq = src + (size_t)(r0 + i) * DIMSZ + h * HD + seg * 32;
        #pragma unroll
        for (int j = 0; j < 8; j++) {
            float4 v = *(const float4*)(gq + 4 * j);
            int d = seg * 32 + 4 * j;
            Qts[(d + 0) * 132 + i] = v.x * SCALE_LOG2;
            Qts[(d + 1) * 132 + i] = v.y * SCALE_LOG2;
            Qts[(d + 2) * 132 + i] = v.z * SCALE_LOG2;
            Qts[(d + 3) * 132 + i] = v.w * SCALE_LOG2;
        }
    }
    if (tid < QT) { rMax[tid] = -1e30f; rLsum[tid] = 0.0f; }

    // S coords: thread = 4q x 8m; mt in lane bits so each q-row spans 8 lanes
    const int mt = tid & 7;          // m-tile (8 m each)
    const int qt = tid >> 3;         // q-tile (4 q each), 0..31
    // PV coords: thread = 4q x 8d
    const int dg = tid & 7;
    const int qg = tid >> 3;
    // loader coords: 64 rows x 64 d; each thread 1 row-quarter (16 d)
    const int lm = tid & 63, lseg = tid >> 6;    // lseg 0..3

    ull Opk[4][4];                   // O[4q][8d as 4 pairs]
    #pragma unroll
    for (int qi = 0; qi < 4; qi++)
        #pragma unroll
        for (int dp = 0; dp < 4; dp++) Opk[qi][dp] = 0ull;

    for (int c = 0; c < NCH; c++) {
        __syncthreads();   // prev PV done reading Ps/Vs; smem writable
        // ---- load K chunk: Kts[d][m] transposed + Vs[m][d] straight ----
        {
            const float* gk = mem + (size_t)(c * MC + lm) * HD + lseg * 16;
            float4 v0 = *(const float4*)gk;
            float4 v1 = *(const float4*)(gk + 4);
            float4 v2 = *(const float4*)(gk + 8);
            float4 v3 = *(const float4*)(gk + 12);
            float* vrow = Vs + lm * 68 + lseg * 16;
            *(float4*)(vrow)      = v0;
            *(float4*)(vrow + 4)  = v1;
            *(float4*)(vrow + 8)  = v2;
            *(float4*)(vrow + 12) = v3;
            const int d0 = lseg * 16;
            float vv[16] = {v0.x, v0.y, v0.z, v0.w, v1.x, v1.y, v1.z, v1.w,
                            v2.x, v2.y, v2.z, v2.w, v3.x, v3.y, v3.z, v3.w};
            #pragma unroll
            for (int j = 0; j < 16; j++)
                Kts[(d0 + j) * 68 + lm] = vv[j];
        }
        __syncthreads();

        // ---- S = Q @ Kc^T : 4q x 8m, pairs along m ----
        ull spk[4][4];
        #pragma unroll
        for (int qi = 0; qi < 4; qi++)
            #pragma unroll
            for (int mp = 0; mp < 4; mp++) spk[qi][mp] = 0ull;

        const float* qbase = Qts + qt * 4;
        const float* kbase = Kts + mt * 8;
        #pragma unroll 8
        for (int d = 0; d < HD; d++) {
            float4 qv = *(const float4*)(qbase + d * 132);              // 4 q (broadcast)
            ulonglong2 ka = *(const ulonglong2*)(kbase + d * 68);       // m pairs 0,1
            ulonglong2 kb = *(const ulonglong2*)(kbase + d * 68 + 4);   // m pairs 2,3
            ull q0 = pack2(qv.x, qv.x);
            ull q1 = pack2(qv.y, qv.y);
            ull q2 = pack2(qv.z, qv.z);
            ull q3 = pack2(qv.w, qv.w);
            ffma2(spk[0][0], q0, ka.x); ffma2(spk[0][1], q0, ka.y);
            ffma2(spk[0][2], q0, kb.x); ffma2(spk[0][3], q0, kb.y);
            ffma2(spk[1][0], q1, ka.x); ffma2(spk[1][1], q1, ka.y);
            ffma2(spk[1][2], q1, kb.x); ffma2(spk[1][3], q1, kb.y);
            ffma2(spk[2][0], q2, ka.x); ffma2(spk[2][1], q2, ka.y);
            ffma2(spk[2][2], q2, kb.x); ffma2(spk[2][3], q2, kb.y);
            ffma2(spk[3][0], q3, ka.x); ffma2(spk[3][1], q3, ka.y);
            ffma2(spk[3][2], q3, kb.x); ffma2(spk[3][3], q3, kb.y);
        }

        // ---- online softmax (base 2); each q row spans the 8 mt lanes ----
        #pragma unroll
        for (int qi = 0; qi < 4; qi++) {
            float s[8];
            unpack2(spk[qi][0], s[0], s[1]);
            unpack2(spk[qi][1], s[2], s[3]);
            unpack2(spk[qi][2], s[4], s[5]);
            unpack2(spk[qi][3], s[6], s[7]);
            float mx = s[0];
            #pragma unroll
            for (int j = 1; j < 8; j++) mx = fmaxf(mx, s[j]);
            #pragma unroll
            for (int o = 4; o >= 1; o >>= 1)
                mx = fmaxf(mx, __shfl_xor_sync(0xffffffffu, mx, o));
            const int q = qt * 4 + qi;
            float mold = rMax[q];
            float mnew = fmaxf(mold, mx);
            float alpha = ex2(mold - mnew);
            float rs = 0.0f;
            #pragma unroll
            for (int j = 0; j < 8; j++) { s[j] = ex2(s[j] - mnew); rs += s[j]; }
            #pragma unroll
            for (int o = 4; o >= 1; o >>= 1)
                rs += __shfl_xor_sync(0xffffffffu, rs, o);
            if (mt == 0) {
                rMax[q]   = mnew;
                rLsum[q]  = rLsum[q] * alpha + rs;
                rAlpha[q] = alpha;
            }
            float4 p0 = {s[0], s[1], s[2], s[3]};
            float4 p1 = {s[4], s[5], s[6], s[7]};
            *(float4*)(Ps + q * 68 + mt * 8)     = p0;
            *(float4*)(Ps + q * 68 + mt * 8 + 4) = p1;
        }
        __syncthreads();

        // ---- PV: O = O*alpha + P @ V over all 64 m rows ----
        {
            #pragma unroll
            for (int qi = 0; qi < 4; qi++) {
                float a = rAlpha[qg + 32 * qi];
                ull ap = pack2(a, a);
                #pragma unroll
                for (int dp = 0; dp < 4; dp++) Opk[qi][dp] = mul2(Opk[qi][dp], ap);
            }
            const float* vbase = Vs + dg * 8;
            #pragma unroll 4
            for (int mm = 0; mm < MC; mm++) {
                const float* vp = vbase + mm * 68;
                ulonglong2 v0 = *(const ulonglong2*)vp;       // d pairs 0,1
                ulonglong2 v1 = *(const ulonglong2*)(vp + 4); // d pairs 2,3
                #pragma unroll
                for (int qi = 0; qi < 4; qi++) {
                    float p = Ps[(qg + 32 * qi) * 68 + mm];
                    ull pd = pack2(p, p);
                    ffma2(Opk[qi][0], pd, v0.x);
                    ffma2(Opk[qi][1], pd, v0.y);
                    ffma2(Opk[qi][2], pd, v1.x);
                    ffma2(Opk[qi][3], pd, v1.y);
                }
            }
        }
    }

    // ---- epilogue: normalize and store ----
    #pragma unroll
    for (int qi = 0; qi < 4; qi++) {
        const int q = qg + 32 * qi;
        float inv = 1.0f / rLsum[q];
        float4 o0, o1;
        unpack2(Opk[qi][0], o0.x, o0.y);
        unpack2(Opk[qi][1], o0.z, o0.w);
        unpack2(Opk[qi][2], o1.x, o1.y);
        unpack2(Opk[qi][3], o1.z, o1.w);
        o0.x *= inv; o0.y *= inv; o0.z *= inv; o0.w *= inv;
        o1.x *= inv; o1.y *= inv; o1.z *= inv; o1.w *= inv;
        float* op = dst + (size_t)(r0 + q) * DIMSZ + h * HD + dg * 8;
        *(float4*)op       = o0;
        *(float4*)(op + 4) = o1;
    }
}

// =======================================================================
extern "C" void kernel_launch(void* const* d_in, const int* in_sizes, int n_in,
                              void* d_out, int out_size)
{
    (void)in_sizes; (void)n_in; (void)out_size;
    const float* x    = (const float*)d_in[0];
    const float* mem  = (const float*)d_in[1];
    const float* Wq   = (const float*)d_in[2];
    const float* bq   = (const float*)d_in[3];
    const float* Wo   = (const float*)d_in[4];
    const float* bo   = (const float*)d_in[5];
    float* out = (float*)d_out;

    float *bufA = nullptr, *bufB = nullptr;
    cudaGetSymbolAddress((void**)&bufA, g_bufA);
    cudaGetSymbolAddress((void**)&bufB, g_bufB);

    cudaFuncSetAttribute(hopfield_attn_kernel,
                         cudaFuncAttributeMaxDynamicSharedMemorySize, SM_BYTES);

    dim3 gemm_grid(DIMSZ / 128, BL / 128);     // (8, 32)
    dim3 attn_grid(BL / QT, NHEADS);           // (32, 16)

    linear_kernel<<<gemm_grid, 256>>>(bufA, x, Wq, bq);
    hopfield_attn_kernel<<<attn_grid, 256, SM_BYTES>>>(bufB, bufA, mem);
    hopfield_attn_kernel<<<attn_grid, 256, SM_BYTES>>>(bufA, bufB, mem);
    linear_kernel<<<gemm_grid, 256>>>(out, bufA, Wo, bo);
}

// round 9
// speedup vs baseline: 2.0194x; 2.0194x over previous
#include <cuda_runtime.h>
#include <cuda_bf16.h>
#include <cstdint>
#include <cstddef>

#define DIMSZ 1024
#define HD 64
#define NHEADS 16
#define BL 4096
#define MROWS 2048
#define MC 64
#define NCH (MROWS/MC)
#define SCALE_LOG2 23.083120654223414f

typedef unsigned long long ull;
typedef uint32_t u32;

__device__ float g_bufA[(size_t)BL*DIMSZ];
__device__ float g_bufB[(size_t)BL*DIMSZ];
__device__ __align__(16) __nv_bfloat16 g_k0[MROWS*HD], g_k1[MROWS*HD], g_k2[MROWS*HD];
__device__ __align__(16) __nv_bfloat16 g_vT0[HD*MROWS], g_vT1[HD*MROWS];
__device__ __align__(16) __nv_bfloat16 g_q0[(size_t)BL*DIMSZ], g_q1[(size_t)BL*DIMSZ], g_q2[(size_t)BL*DIMSZ];

__device__ __forceinline__ ull pack2(float lo,float hi){ull r;asm("mov.b64 %0,{%1,%2};":"=l"(r):"f"(lo),"f"(hi));return r;}
__device__ __forceinline__ void unpack2(ull v,float&lo,float&hi){asm("mov.b64 {%0,%1},%2;":"=f"(lo),"=f"(hi):"l"(v));}
__device__ __forceinline__ void ffma2(ull&d,ull a,ull b){asm("fma.rn.f32x2 %0,%1,%2,%0;":"+l"(d):"l"(a),"l"(b));}
__device__ __forceinline__ float ex2(float x){float r;asm("ex2.approx.f32 %0,%1;":"=f"(r):"f"(x));return r;}
__device__ __forceinline__ u32 smem_u32(const void*p){u32 a;asm("{ .reg .u64 t; cvta.to.shared.u64 t,%1; cvt.u32.u64 %0,t; }":"=r"(a):"l"(p));return a;}
__device__ __forceinline__ u32 packbf(__nv_bfloat16 lo,__nv_bfloat16 hi){return (u32)__bfloat16_as_ushort(lo)|((u32)__bfloat16_as_ushort(hi)<<16);}
__device__ __forceinline__ void split3(float s,__nv_bfloat16&a,__nv_bfloat16&b,__nv_bfloat16&c){
    a=__float2bfloat16(s); float r=s-__bfloat162float(a);
    b=__float2bfloat16(r); c=__float2bfloat16(r-__bfloat162float(b));
}
__device__ __forceinline__ void ldmx4(u32* r,u32 a){
    asm volatile("ldmatrix.sync.aligned.m8n8.x4.shared.b16 {%0,%1,%2,%3},[%4];"
        :"=r"(r[0]),"=r"(r[1]),"=r"(r[2]),"=r"(r[3]):"r"(a));
}
__device__ __forceinline__ void ldmx2(u32* r,u32 a){
    asm volatile("ldmatrix.sync.aligned.m8n8.x2.shared.b16 {%0,%1},[%2];"
        :"=r"(r[0]),"=r"(r[1]):"r"(a));
}
__device__ __forceinline__ void mma16816(float* c,const u32* a,const u32* b){
    asm volatile("mma.sync.aligned.m16n8k16.row.col.f32.bf16.bf16.f32 "
        "{%0,%1,%2,%3},{%4,%5,%6,%7},{%8,%9},{%0,%1,%2,%3};"
        :"+f"(c[0]),"+f"(c[1]),"+f"(c[2]),"+f"(c[3])
        :"r"(a[0]),"r"(a[1]),"r"(a[2]),"r"(a[3]),"r"(b[0]),"r"(b[1]));
}

// ---------------- linear (R2-proven, 232us) ----------------
__global__ void __launch_bounds__(256,2)
linear_kernel(float* __restrict__ C,const float* __restrict__ A,const float* __restrict__ W,const float* __restrict__ bias){
    __shared__ float As[16][132], Bs[16][132];
    const int tid=threadIdx.x, tx=tid&15, ty=tid>>4;
    const int i0=blockIdx.y*128, j0=blockIdx.x*128;
    ull acc[8][4];
    {
        const float* bp=bias+j0+tx*8;
        float4 b0=*(const float4*)bp, b1=*(const float4*)(bp+4);
        ull p0=pack2(b0.x,b0.y),p1=pack2(b0.z,b0.w),p2=pack2(b1.x,b1.y),p3=pack2(b1.z,b1.w);
        #pragma unroll
        for(int ii=0;ii<8;ii++){acc[ii][0]=p0;acc[ii][1]=p1;acc[ii][2]=p2;acc[ii][3]=p3;}
    }
    const int lk=tid&15, ib=tid>>4;
    for(int kt=0;kt<64;kt++){
        __syncthreads();
        const float* Ag=A+(size_t)(i0+ib)*DIMSZ+kt*16+lk;
        const float* Wg=W+(size_t)(j0+ib)*DIMSZ+kt*16+lk;
        #pragma unroll
        for(int rep=0;rep<8;rep++){
            As[lk][ib+rep*16]=Ag[(size_t)rep*16*DIMSZ];
            Bs[lk][ib+rep*16]=Wg[(size_t)rep*16*DIMSZ];
        }
        __syncthreads();
        #pragma unroll
        for(int k=0;k<16;k++){
            const float* ap=&As[k][ty*8];
            float4 a0=*(const float4*)ap, a1=*(const float4*)(ap+4);
            const float* bp=&Bs[k][tx*8];
            ulonglong2 w0=*(const ulonglong2*)bp, w1=*(const ulonglong2*)(bp+4);
            float a[8]={a0.x,a0.y,a0.z,a0.w,a1.x,a1.y,a1.z,a1.w};
            #pragma unroll
            for(int ii=0;ii<8;ii++){
                ull ad=pack2(a[ii],a[ii]);
                ffma2(acc[ii][0],ad,w0.x);ffma2(acc[ii][1],ad,w0.y);
                ffma2(acc[ii][2],ad,w1.x);ffma2(acc[ii][3],ad,w1.y);
            }
        }
    }
    #pragma unroll
    for(int ii=0;ii<8;ii++){
        float4 o0,o1;
        unpack2(acc[ii][0],o0.x,o0.y);unpack2(acc[ii][1],o0.z,o0.w);
        unpack2(acc[ii][2],o1.x,o1.y);unpack2(acc[ii][3],o1.z,o1.w);
        float* cp=C+(size_t)(i0+ty*8+ii)*DIMSZ+j0+tx*8;
        *(float4*)cp=o0; *(float4*)(cp+4)=o1;
    }
}

// ---------------- prep kernels ----------------
__global__ void mem_split_kernel(const float* __restrict__ mem){
    int i=blockIdx.x*256+threadIdx.x;
    if(i>=MROWS*HD) return;
    int m=i>>6, d=i&63;
    float v=mem[i];
    __nv_bfloat16 b0,b1,b2; split3(v,b0,b1,b2);
    g_k0[i]=b0; g_k1[i]=b1; g_k2[i]=b2;
    g_vT0[d*MROWS+m]=b0; g_vT1[d*MROWS+m]=b1;
}
__global__ void qsplit_kernel(const float* __restrict__ src){
    size_t i2=((size_t)blockIdx.x*256+threadIdx.x)*2;
    float2 v=*(const float2*)(src+i2);
    __nv_bfloat16 x0,x1,x2,y0,y1,y2;
    split3(v.x*SCALE_LOG2,x0,x1,x2);
    split3(v.y*SCALE_LOG2,y0,y1,y2);
    *(u32*)&g_q0[i2]=packbf(x0,y0);
    *(u32*)&g_q1[i2]=packbf(x1,y1);
    *(u32*)&g_q2[i2]=packbf(x2,y2);
}

// ---------------- warp-mma flash Hopfield iteration ----------------
// smem: rows of 64 bf16 padded to 80 (160B, 16B-aligned for ldmatrix)
#define STRB 160
#define OQ(s)  ((s)*20480)           // Q splits: 128 rows
#define OKS(s) (61440+(s)*10240)     // K splits: 64 rows
#define OV(s)  (92160+(s)*10240)     // Vt splits: 64 d-rows x 64 m
#define SMEM_AT 112640

__global__ void __launch_bounds__(256,2)
hopfield_mma_kernel(float* __restrict__ dst){
    extern __shared__ char smc[];
    const u32 sb=smem_u32(smc);
    const int tid=threadIdx.x, wid=tid>>5, lane=tid&31;
    const int h=blockIdx.y, r0=blockIdx.x*128;

    { // load Q splits [128][64]
        const __nv_bfloat16* gq[3]={g_q0,g_q1,g_q2};
        #pragma unroll
        for(int s=0;s<3;s++)
            #pragma unroll
            for(int j=0;j<4;j++){
                int idx=tid+256*j, row=idx>>3, c16=idx&7;
                *(uint4*)(smc+OQ(s)+row*STRB+c16*16)
                    =*(const uint4*)(gq[s]+(size_t)(r0+row)*DIMSZ+h*HD+c16*8);
            }
    }

    // ldmatrix per-thread address components
    const u32 a_off=(u32)((wid*16+(lane&15))*STRB+((lane>>4)<<3)*2); // + kt*32
    const int bl=lane&15, brow=bl&7, bhi=(bl&8)?8:0;

    float ma=-1e30f,mb=-1e30f,la=0.0f,lb=0.0f;
    float oacc[8][4];
    #pragma unroll
    for(int i=0;i<8;i++){oacc[i][0]=0;oacc[i][1]=0;oacc[i][2]=0;oacc[i][3]=0;}

    for(int c=0;c<NCH;c++){
        __syncthreads();
        { // load K splits + Vt splits (each 64x64)
            const __nv_bfloat16* gk[3]={g_k0,g_k1,g_k2};
            #pragma unroll
            for(int s=0;s<3;s++)
                #pragma unroll
                for(int j=0;j<2;j++){
                    int idx=tid+256*j, row=idx>>3, c16=idx&7;
                    *(uint4*)(smc+OKS(s)+row*STRB+c16*16)
                        =*(const uint4*)(gk[s]+(size_t)(c*MC+row)*HD+c16*8);
                }
            const __nv_bfloat16* gv[2]={g_vT0,g_vT1};
            #pragma unroll
            for(int s=0;s<2;s++)
                #pragma unroll
                for(int j=0;j<2;j++){
                    int idx=tid+256*j, row=idx>>3, c16=idx&7;
                    *(uint4*)(smc+OV(s)+row*STRB+c16*16)
                        =*(const uint4*)(gv[s]+(size_t)row*MROWS+c*MC+c16*8);
                }
        }
        __syncthreads();

        // ---- S = Q@K^T with 6 split products ----
        float sacc[8][4];
        #pragma unroll
        for(int i=0;i<8;i++){sacc[i][0]=0;sacc[i][1]=0;sacc[i][2]=0;sacc[i][3]=0;}
        #pragma unroll
        for(int kt=0;kt<4;kt++){
            u32 aq[3][4];
            #pragma unroll
            for(int qs=0;qs<3;qs++) ldmx4(aq[qs],sb+OQ(qs)+a_off+kt*32);
            #pragma unroll
            for(int nt=0;nt<8;nt++){
                u32 b0[2],b1[2],b2[2];
                u32 boff=(u32)((nt*8+brow)*STRB+(kt*16+bhi)*2);
                ldmx2(b0,sb+OKS(0)+boff);
                ldmx2(b1,sb+OKS(1)+boff);
                ldmx2(b2,sb+OKS(2)+boff);
                mma16816(sacc[nt],aq[0],b0);
                mma16816(sacc[nt],aq[1],b0);
                mma16816(sacc[nt],aq[2],b0);
                mma16816(sacc[nt],aq[0],b1);
                mma16816(sacc[nt],aq[1],b1);
                mma16816(sacc[nt],aq[0],b2);
            }
        }

        // ---- online softmax (base 2); rows qa=lane/4, qb=qa+8 in warp band ----
        float mxa=-1e30f,mxb=-1e30f;
        #pragma unroll
        for(int nt=0;nt<8;nt++){
            mxa=fmaxf(mxa,fmaxf(sacc[nt][0],sacc[nt][1]));
            mxb=fmaxf(mxb,fmaxf(sacc[nt][2],sacc[nt][3]));
        }
        mxa=fmaxf(mxa,__shfl_xor_sync(0xffffffffu,mxa,1));
        mxa=fmaxf(mxa,__shfl_xor_sync(0xffffffffu,mxa,2));
        mxb=fmaxf(mxb,__shfl_xor_sync(0xffffffffu,mxb,1));
        mxb=fmaxf(mxb,__shfl_xor_sync(0xffffffffu,mxb,2));
        float mna=fmaxf(ma,mxa), mnb=fmaxf(mb,mxb);
        float ala=ex2(ma-mna), alb=ex2(mb-mnb);
        ma=mna; mb=mnb;
        float rsa=0.0f, rsb=0.0f;
        #pragma unroll
        for(int nt=0;nt<8;nt++){
            sacc[nt][0]=ex2(sacc[nt][0]-mna);
            sacc[nt][1]=ex2(sacc[nt][1]-mna);
            sacc[nt][2]=ex2(sacc[nt][2]-mnb);
            sacc[nt][3]=ex2(sacc[nt][3]-mnb);
            rsa+=sacc[nt][0]+sacc[nt][1];
            rsb+=sacc[nt][2]+sacc[nt][3];
        }
        rsa+=__shfl_xor_sync(0xffffffffu,rsa,1);
        rsa+=__shfl_xor_sync(0xffffffffu,rsa,2);
        rsb+=__shfl_xor_sync(0xffffffffu,rsb,1);
        rsb+=__shfl_xor_sync(0xffffffffu,rsb,2);
        la=la*ala+rsa; lb=lb*alb+rsb;
        #pragma unroll
        for(int dt=0;dt<8;dt++){
            oacc[dt][0]*=ala; oacc[dt][1]*=ala;
            oacc[dt][2]*=alb; oacc[dt][3]*=alb;
        }
        // P -> A-fragments (hi + lo splits), in registers
        u32 pha[4][4], pla[4][4];
        #pragma unroll
        for(int kt=0;kt<4;kt++){
            const int n0=2*kt, n1=2*kt+1;
            #pragma unroll
            for(int half=0;half<2;half++){
                const int nt=half?n1:n0;
                #pragma unroll
                for(int rr=0;rr<2;rr++){
                    float p0=sacc[nt][rr*2], p1=sacc[nt][rr*2+1];
                    __nv_bfloat16 h0=__float2bfloat16(p0), h1=__float2bfloat16(p1);
                    __nv_bfloat16 l0=__float2bfloat16(p0-__bfloat162float(h0));
                    __nv_bfloat16 l1=__float2bfloat16(p1-__bfloat162float(h1));
                    pha[kt][half*2+rr]=packbf(h0,h1);
                    pla[kt][half*2+rr]=packbf(l0,l1);
                }
            }
        }

        // ---- PV: O += (Ph+Pl)V0 + Ph V1 ----
        #pragma unroll
        for(int kt=0;kt<4;kt++){
            #pragma unroll
            for(int dt=0;dt<8;dt++){
                u32 bv0[2],bv1[2];
                u32 boff=(u32)((dt*8+brow)*STRB+(kt*16+bhi)*2);
                ldmx2(bv0,sb+OV(0)+boff);
                ldmx2(bv1,sb+OV(1)+boff);
                mma16816(oacc[dt],pha[kt],bv0);
                mma16816(oacc[dt],pla[kt],bv0);
                mma16816(oacc[dt],pha[kt],bv1);
            }
        }
    }

    // ---- epilogue: normalize, store fp32 + next-iter Q splits ----
    {
        const float inva=1.0f/la, invb=1.0f/lb;
        const int qa=r0+wid*16+(lane>>2), qb=qa+8;
        const size_t basea=(size_t)qa*DIMSZ+h*HD, baseb=(size_t)qb*DIMSZ+h*HD;
        #pragma unroll
        for(int dt=0;dt<8;dt++){
            const int d=dt*8+2*(lane&3);
            float v0=oacc[dt][0]*inva, v1=oacc[dt][1]*inva;
            float v2=oacc[dt][2]*invb, v3=oacc[dt][3]*invb;
            *(float2*)(dst+basea+d)=make_float2(v0,v1);
            *(float2*)(dst+baseb+d)=make_float2(v2,v3);
            __nv_bfloat16 x0,x1,x2,y0,y1,y2;
            split3(v0*SCALE_LOG2,x0,x1,x2); split3(v1*SCALE_LOG2,y0,y1,y2);
            *(u32*)&g_q0[basea+d]=packbf(x0,y0);
            *(u32*)&g_q1[basea+d]=packbf(x1,y1);
            *(u32*)&g_q2[basea+d]=packbf(x2,y2);
            split3(v2*SCALE_LOG2,x0,x1,x2); split3(v3*SCALE_LOG2,y0,y1,y2);
            *(u32*)&g_q0[baseb+d]=packbf(x0,y0);
            *(u32*)&g_q1[baseb+d]=packbf(x1,y1);
            *(u32*)&g_q2[baseb+d]=packbf(x2,y2);
        }
    }
}

extern "C" void kernel_launch(void* const* d_in, const int* in_sizes, int n_in,
                              void* d_out, int out_size){
    (void)in_sizes;(void)n_in;(void)out_size;
    const float* x=(const float*)d_in[0];
    const float* mem=(const float*)d_in[1];
    const float* Wq=(const float*)d_in[2];
    const float* bq=(const float*)d_in[3];
    const float* Wo=(const float*)d_in[4];
    const float* bo=(const float*)d_in[5];
    float* out=(float*)d_out;

    float *bufA=nullptr,*bufB=nullptr;
    cudaGetSymbolAddress((void**)&bufA,g_bufA);
    cudaGetSymbolAddress((void**)&bufB,g_bufB);
    cudaFuncSetAttribute(hopfield_mma_kernel,cudaFuncAttributeMaxDynamicSharedMemorySize,SMEM_AT);

    dim3 gg(DIMSZ/128,BL/128), ag(BL/128,NHEADS);
    linear_kernel<<<gg,256>>>(bufA,x,Wq,bq);
    mem_split_kernel<<<(MROWS*HD+255)/256,256>>>(mem);
    qsplit_kernel<<<(u32)((size_t)BL*DIMSZ/2/256),256>>>(bufA);
    hopfield_mma_kernel<<<ag,256,SMEM_AT>>>(bufB);
    hopfield_mma_kernel<<<ag,256,SMEM_AT>>>(bufA);
    linear_kernel<<<gg,256>>>(out,bufA,Wo,bo);
}

// round 10
// speedup vs baseline: 2.3032x; 1.1406x over previous
#include <cuda_runtime.h>
#include <cuda_bf16.h>
#include <cstdint>
#include <cstddef>

#define DIMSZ 1024
#define HD 64
#define NHEADS 16
#define BL 4096
#define MROWS 2048
#define MC 64
#define NCH (MROWS/MC)
#define SCALE_LOG2 23.083120654223414f

typedef unsigned long long ull;
typedef uint32_t u32;

__device__ float g_bufA[(size_t)BL*DIMSZ];
__device__ float g_bufB[(size_t)BL*DIMSZ];
__device__ __align__(16) __nv_bfloat16 g_k0[MROWS*HD], g_k1[MROWS*HD], g_k2[MROWS*HD];
__device__ __align__(16) __nv_bfloat16 g_vT0[HD*MROWS], g_vT1[HD*MROWS];
__device__ __align__(16) __nv_bfloat16 g_q0[(size_t)BL*DIMSZ], g_q1[(size_t)BL*DIMSZ], g_q2[(size_t)BL*DIMSZ];

__device__ __forceinline__ ull pack2(float lo,float hi){ull r;asm("mov.b64 %0,{%1,%2};":"=l"(r):"f"(lo),"f"(hi));return r;}
__device__ __forceinline__ void unpack2(ull v,float&lo,float&hi){asm("mov.b64 {%0,%1},%2;":"=f"(lo),"=f"(hi):"l"(v));}
__device__ __forceinline__ void ffma2(ull&d,ull a,ull b){asm("fma.rn.f32x2 %0,%1,%2,%0;":"+l"(d):"l"(a),"l"(b));}
__device__ __forceinline__ float ex2(float x){float r;asm("ex2.approx.f32 %0,%1;":"=f"(r):"f"(x));return r;}
__device__ __forceinline__ u32 smem_u32(const void*p){u32 a;asm("{ .reg .u64 t; cvta.to.shared.u64 t,%1; cvt.u32.u64 %0,t; }":"=r"(a):"l"(p));return a;}
__device__ __forceinline__ u32 packbf(__nv_bfloat16 lo,__nv_bfloat16 hi){return (u32)__bfloat16_as_ushort(lo)|((u32)__bfloat16_as_ushort(hi)<<16);}
__device__ __forceinline__ void split3(float s,__nv_bfloat16&a,__nv_bfloat16&b,__nv_bfloat16&c){
    a=__float2bfloat16(s); float r=s-__bfloat162float(a);
    b=__float2bfloat16(r); c=__float2bfloat16(r-__bfloat162float(b));
}
__device__ __forceinline__ void ldmx4(u32* r,u32 a){
    asm volatile("ldmatrix.sync.aligned.m8n8.x4.shared.b16 {%0,%1,%2,%3},[%4];"
        :"=r"(r[0]),"=r"(r[1]),"=r"(r[2]),"=r"(r[3]):"r"(a));
}
__device__ __forceinline__ void mma16816(float* c,const u32* a,const u32* b){
    asm volatile("mma.sync.aligned.m16n8k16.row.col.f32.bf16.bf16.f32 "
        "{%0,%1,%2,%3},{%4,%5,%6,%7},{%8,%9},{%0,%1,%2,%3};"
        :"+f"(c[0]),"+f"(c[1]),"+f"(c[2]),"+f"(c[3])
        :"r"(a[0]),"r"(a[1]),"r"(a[2]),"r"(a[3]),"r"(b[0]),"r"(b[1]));
}

// ---------------- linear (R2-proven, 232us) ----------------
__global__ void __launch_bounds__(256,2)
linear_kernel(float* __restrict__ C,const float* __restrict__ A,const float* __restrict__ W,const float* __restrict__ bias){
    __shared__ float As[16][132], Bs[16][132];
    const int tid=threadIdx.x, tx=tid&15, ty=tid>>4;
    const int i0=blockIdx.y*128, j0=blockIdx.x*128;
    ull acc[8][4];
    {
        const float* bp=bias+j0+tx*8;
        float4 b0=*(const float4*)bp, b1=*(const float4*)(bp+4);
        ull p0=pack2(b0.x,b0.y),p1=pack2(b0.z,b0.w),p2=pack2(b1.x,b1.y),p3=pack2(b1.z,b1.w);
        #pragma unroll
        for(int ii=0;ii<8;ii++){acc[ii][0]=p0;acc[ii][1]=p1;acc[ii][2]=p2;acc[ii][3]=p3;}
    }
    const int lk=tid&15, ib=tid>>4;
    for(int kt=0;kt<64;kt++){
        __syncthreads();
        const float* Ag=A+(size_t)(i0+ib)*DIMSZ+kt*16+lk;
        const float* Wg=W+(size_t)(j0+ib)*DIMSZ+kt*16+lk;
        #pragma unroll
        for(int rep=0;rep<8;rep++){
            As[lk][ib+rep*16]=Ag[(size_t)rep*16*DIMSZ];
            Bs[lk][ib+rep*16]=Wg[(size_t)rep*16*DIMSZ];
        }
        __syncthreads();
        #pragma unroll
        for(int k=0;k<16;k++){
            const float* ap=&As[k][ty*8];
            float4 a0=*(const float4*)ap, a1=*(const float4*)(ap+4);
            const float* bp=&Bs[k][tx*8];
            ulonglong2 w0=*(const ulonglong2*)bp, w1=*(const ulonglong2*)(bp+4);
            float a[8]={a0.x,a0.y,a0.z,a0.w,a1.x,a1.y,a1.z,a1.w};
            #pragma unroll
            for(int ii=0;ii<8;ii++){
                ull ad=pack2(a[ii],a[ii]);
                ffma2(acc[ii][0],ad,w0.x);ffma2(acc[ii][1],ad,w0.y);
                ffma2(acc[ii][2],ad,w1.x);ffma2(acc[ii][3],ad,w1.y);
            }
        }
    }
    #pragma unroll
    for(int ii=0;ii<8;ii++){
        float4 o0,o1;
        unpack2(acc[ii][0],o0.x,o0.y);unpack2(acc[ii][1],o0.z,o0.w);
        unpack2(acc[ii][2],o1.x,o1.y);unpack2(acc[ii][3],o1.z,o1.w);
        float* cp=C+(size_t)(i0+ty*8+ii)*DIMSZ+j0+tx*8;
        *(float4*)cp=o0; *(float4*)(cp+4)=o1;
    }
}

// ---------------- prep kernels ----------------
__global__ void mem_split_kernel(const float* __restrict__ mem){
    int i=blockIdx.x*256+threadIdx.x;
    if(i>=MROWS*HD) return;
    int m=i>>6, d=i&63;
    float v=mem[i];
    __nv_bfloat16 b0,b1,b2; split3(v,b0,b1,b2);
    g_k0[i]=b0; g_k1[i]=b1; g_k2[i]=b2;
    g_vT0[d*MROWS+m]=b0; g_vT1[d*MROWS+m]=b1;
}
__global__ void qsplit_kernel(const float* __restrict__ src){
    size_t i2=((size_t)blockIdx.x*256+threadIdx.x)*2;
    float2 v=*(const float2*)(src+i2);
    __nv_bfloat16 x0,x1,x2,y0,y1,y2;
    split3(v.x*SCALE_LOG2,x0,x1,x2);
    split3(v.y*SCALE_LOG2,y0,y1,y2);
    *(u32*)&g_q0[i2]=packbf(x0,y0);
    *(u32*)&g_q1[i2]=packbf(x1,y1);
    *(u32*)&g_q2[i2]=packbf(x2,y2);
}

// ---------------- warp-mma flash Hopfield iteration ----------------
// XOR-swizzled smem: row stride 128B, 16B chunk c stored at c^(row&7).
// Conflict-free for all ldmatrix and STS.128 accesses.
#define OQ(s)  ((s)*16384)           // Q splits: 128 rows x 128B
#define OKS(s) (49152+(s)*8192)      // K splits: 64 rows
#define OV(s)  (73728+(s)*8192)      // Vt splits: 64 d-rows x 64 m
#define SMEM_AT 90112

__global__ void __launch_bounds__(256,2)
hopfield_mma_kernel(float* __restrict__ dst){
    extern __shared__ char smc[];
    const u32 sb=smem_u32(smc);
    const int tid=threadIdx.x, wid=tid>>5, lane=tid&31;
    const int h=blockIdx.y, r0=blockIdx.x*128;

    { // load Q splits [128][64] swizzled
        const __nv_bfloat16* gq[3]={g_q0,g_q1,g_q2};
        #pragma unroll
        for(int s=0;s<3;s++)
            #pragma unroll
            for(int j=0;j<4;j++){
                int idx=tid+256*j, row=idx>>3, c=idx&7;
                *(uint4*)(smc+OQ(s)+row*128+((c^(row&7))<<4))
                    =*(const uint4*)(gq[s]+(size_t)(r0+row)*DIMSZ+h*HD+c*8);
            }
    }

    // ldmatrix address components
    const int arow=wid*16+(lane&15);           // A row
    const u32 arow128=(u32)(arow*128);
    const int arx=arow&7, acs=lane>>4;         // A chunk sel (0/1)
    const int browB=((lane>>4)<<3)+(lane&7);   // B row within 16-row pair
    const int kcB=(lane>>3)&1;                 // B k-chunk sel (0/1)

    float ma=-1e30f,mb=-1e30f,la=0.0f,lb=0.0f;
    float oacc[8][4];
    #pragma unroll
    for(int i=0;i<8;i++){oacc[i][0]=0;oacc[i][1]=0;oacc[i][2]=0;oacc[i][3]=0;}

    for(int c=0;c<NCH;c++){
        __syncthreads();
        { // load K splits + Vt splits (each 64x64) swizzled
            const __nv_bfloat16* gk[3]={g_k0,g_k1,g_k2};
            #pragma unroll
            for(int s=0;s<3;s++)
                #pragma unroll
                for(int j=0;j<2;j++){
                    int idx=tid+256*j, row=idx>>3, cc=idx&7;
                    *(uint4*)(smc+OKS(s)+row*128+((cc^(row&7))<<4))
                        =*(const uint4*)(gk[s]+(size_t)(c*MC+row)*HD+cc*8);
                }
            const __nv_bfloat16* gv[2]={g_vT0,g_vT1};
            #pragma unroll
            for(int s=0;s<2;s++)
                #pragma unroll
                for(int j=0;j<2;j++){
                    int idx=tid+256*j, row=idx>>3, cc=idx&7;
                    *(uint4*)(smc+OV(s)+row*128+((cc^(row&7))<<4))
                        =*(const uint4*)(gv[s]+(size_t)row*MROWS+c*MC+cc*8);
                }
        }
        __syncthreads();

        // ---- S = Q@K^T, 6 split products, x4 B loads (2 n-tiles/load) ----
        float sacc[8][4];
        #pragma unroll
        for(int i=0;i<8;i++){sacc[i][0]=0;sacc[i][1]=0;sacc[i][2]=0;sacc[i][3]=0;}
        #pragma unroll
        for(int kt=0;kt<4;kt++){
            u32 aq[3][4];
            const u32 ca=arow128+(u32)(((kt*2+acs)^arx)<<4);
            ldmx4(aq[0],sb+OQ(0)+ca);
            ldmx4(aq[1],sb+OQ(1)+ca);
            ldmx4(aq[2],sb+OQ(2)+ca);
            #pragma unroll
            for(int ntp=0;ntp<4;ntp++){
                const int rowB=ntp*16+browB;
                const u32 offB=(u32)(rowB*128)+(u32)((((kt*2+kcB))^(rowB&7))<<4);
                u32 b0[4],b1[4],b2[4];
                ldmx4(b0,sb+OKS(0)+offB);
                ldmx4(b1,sb+OKS(1)+offB);
                ldmx4(b2,sb+OKS(2)+offB);
                float* s0=sacc[2*ntp]; float* s1=sacc[2*ntp+1];
                mma16816(s0,aq[0],b0);   mma16816(s0,aq[1],b0);   mma16816(s0,aq[2],b0);
                mma16816(s0,aq[0],b1);   mma16816(s0,aq[1],b1);   mma16816(s0,aq[0],b2);
                mma16816(s1,aq[0],b0+2); mma16816(s1,aq[1],b0+2); mma16816(s1,aq[2],b0+2);
                mma16816(s1,aq[0],b1+2); mma16816(s1,aq[1],b1+2); mma16816(s1,aq[0],b2+2);
            }
        }

        // ---- online softmax (base 2) ----
        float mxa=-1e30f,mxb=-1e30f;
        #pragma unroll
        for(int nt=0;nt<8;nt++){
            mxa=fmaxf(mxa,fmaxf(sacc[nt][0],sacc[nt][1]));
            mxb=fmaxf(mxb,fmaxf(sacc[nt][2],sacc[nt][3]));
        }
        mxa=fmaxf(mxa,__shfl_xor_sync(0xffffffffu,mxa,1));
        mxa=fmaxf(mxa,__shfl_xor_sync(0xffffffffu,mxa,2));
        mxb=fmaxf(mxb,__shfl_xor_sync(0xffffffffu,mxb,1));
        mxb=fmaxf(mxb,__shfl_xor_sync(0xffffffffu,mxb,2));
        float mna=fmaxf(ma,mxa), mnb=fmaxf(mb,mxb);
        float ala=ex2(ma-mna), alb=ex2(mb-mnb);
        ma=mna; mb=mnb;
        float rsa=0.0f, rsb=0.0f;
        #pragma unroll
        for(int nt=0;nt<8;nt++){
            sacc[nt][0]=ex2(sacc[nt][0]-mna);
            sacc[nt][1]=ex2(sacc[nt][1]-mna);
            sacc[nt][2]=ex2(sacc[nt][2]-mnb);
            sacc[nt][3]=ex2(sacc[nt][3]-mnb);
            rsa+=sacc[nt][0]+sacc[nt][1];
            rsb+=sacc[nt][2]+sacc[nt][3];
        }
        rsa+=__shfl_xor_sync(0xffffffffu,rsa,1);
        rsa+=__shfl_xor_sync(0xffffffffu,rsa,2);
        rsb+=__shfl_xor_sync(0xffffffffu,rsb,1);
        rsb+=__shfl_xor_sync(0xffffffffu,rsb,2);
        la=la*ala+rsa; lb=lb*alb+rsb;
        #pragma unroll
        for(int dt=0;dt<8;dt++){
            oacc[dt][0]*=ala; oacc[dt][1]*=ala;
            oacc[dt][2]*=alb; oacc[dt][3]*=alb;
        }

        // ---- PV per kt: pack P frags (8 regs live), then x4 V loads ----
        #pragma unroll
        for(int kt=0;kt<4;kt++){
            u32 ph[4], pl[4];
            #pragma unroll
            for(int half=0;half<2;half++){
                const int nt=2*kt+half;
                #pragma unroll
                for(int rr=0;rr<2;rr++){
                    float p0=sacc[nt][rr*2], p1=sacc[nt][rr*2+1];
                    __nv_bfloat16 h0=__float2bfloat16(p0), h1=__float2bfloat16(p1);
                    __nv_bfloat16 l0=__float2bfloat16(p0-__bfloat162float(h0));
                    __nv_bfloat16 l1=__float2bfloat16(p1-__bfloat162float(h1));
                    ph[half*2+rr]=packbf(h0,h1);
                    pl[half*2+rr]=packbf(l0,l1);
                }
            }
            #pragma unroll
            for(int dtp=0;dtp<4;dtp++){
                const int rowB=dtp*16+browB;
                const u32 offV=(u32)(rowB*128)+(u32)((((kt*2+kcB))^(rowB&7))<<4);
                u32 bv0[4],bv1[4];
                ldmx4(bv0,sb+OV(0)+offV);
                ldmx4(bv1,sb+OV(1)+offV);
                float* o0=oacc[2*dtp]; float* o1=oacc[2*dtp+1];
                mma16816(o0,ph,bv0);   mma16816(o0,pl,bv0);   mma16816(o0,ph,bv1);
                mma16816(o1,ph,bv0+2); mma16816(o1,pl,bv0+2); mma16816(o1,ph,bv1+2);
            }
        }
    }

    // ---- epilogue: normalize, store fp32 + next-iter Q splits ----
    {
        const float inva=1.0f/la, invb=1.0f/lb;
        const int qa=r0+wid*16+(lane>>2), qb=qa+8;
        const size_t basea=(size_t)qa*DIMSZ+h*HD, baseb=(size_t)qb*DIMSZ+h*HD;
        #pragma unroll
        for(int dt=0;dt<8;dt++){
            const int d=dt*8+2*(lane&3);
            float v0=oacc[dt][0]*inva, v1=oacc[dt][1]*inva;
            float v2=oacc[dt][2]*invb, v3=oacc[dt][3]*invb;
            *(float2*)(dst+basea+d)=make_float2(v0,v1);
            *(float2*)(dst+baseb+d)=make_float2(v2,v3);
            __nv_bfloat16 x0,x1,x2,y0,y1,y2;
            split3(v0*SCALE_LOG2,x0,x1,x2); split3(v1*SCALE_LOG2,y0,y1,y2);
            *(u32*)&g_q0[basea+d]=packbf(x0,y0);
            *(u32*)&g_q1[basea+d]=packbf(x1,y1);
            *(u32*)&g_q2[basea+d]=packbf(x2,y2);
            split3(v2*SCALE_LOG2,x0,x1,x2); split3(v3*SCALE_LOG2,y0,y1,y2);
            *(u32*)&g_q0[baseb+d]=packbf(x0,y0);
            *(u32*)&g_q1[baseb+d]=packbf(x1,y1);
            *(u32*)&g_q2[baseb+d]=packbf(x2,y2);
        }
    }
}

extern "C" void kernel_launch(void* const* d_in, const int* in_sizes, int n_in,
                              void* d_out, int out_size){
    (void)in_sizes;(void)n_in;(void)out_size;
    const float* x=(const float*)d_in[0];
    const float* mem=(const float*)d_in[1];
    const float* Wq=(const float*)d_in[2];
    const float* bq=(const float*)d_in[3];
    const float* Wo=(const float*)d_in[4];
    const float* bo=(const float*)d_in[5];
    float* out=(float*)d_out;

    float *bufA=nullptr,*bufB=nullptr;
    cudaGetSymbolAddress((void**)&bufA,g_bufA);
    cudaGetSymbolAddress((void**)&bufB,g_bufB);
    cudaFuncSetAttribute(hopfield_mma_kernel,cudaFuncAttributeMaxDynamicSharedMemorySize,SMEM_AT);

    dim3 gg(DIMSZ/128,BL/128), ag(BL/128,NHEADS);
    linear_kernel<<<gg,256>>>(bufA,x,Wq,bq);
    mem_split_kernel<<<(MROWS*HD+255)/256,256>>>(mem);
    qsplit_kernel<<<(u32)((size_t)BL*DIMSZ/2/256),256>>>(bufA);
    hopfield_mma_kernel<<<ag,256,SMEM_AT>>>(bufB);
    hopfield_mma_kernel<<<ag,256,SMEM_AT>>>(bufA);
    linear_kernel<<<gg,256>>>(out,bufA,Wo,bo);
}

// round 12
// speedup vs baseline: 2.5504x; 1.1073x over previous
#include <cuda_runtime.h>
#include <cuda_bf16.h>
#include <cstdint>
#include <cstddef>

#define DIMSZ 1024
#define HD 64
#define NHEADS 16
#define BL 4096
#define MROWS 2048
#define MC 64
#define NCH (MROWS/MC)
#define SCALE_LOG2 23.083120654223414f
#define INV_SCALE  (1.0f/SCALE_LOG2)

typedef unsigned long long ull;
typedef uint32_t u32;

__device__ float g_bufA[(size_t)BL*DIMSZ];
__device__ float g_bufB[(size_t)BL*DIMSZ];
__device__ __align__(16) __nv_bfloat16 g_k0[MROWS*HD], g_k1[MROWS*HD], g_k2[MROWS*HD];
__device__ __align__(16) __nv_bfloat16 g_vT0[HD*MROWS], g_vT1[HD*MROWS];
__device__ __align__(16) __nv_bfloat16 g_q0[(size_t)BL*DIMSZ], g_q1[(size_t)BL*DIMSZ], g_q2[(size_t)BL*DIMSZ];
__device__ __align__(16) __nv_bfloat16 g_x0[(size_t)BL*DIMSZ], g_x1[(size_t)BL*DIMSZ], g_x2[(size_t)BL*DIMSZ];
__device__ __align__(16) __nv_bfloat16 g_wq0[DIMSZ*DIMSZ], g_wq1[DIMSZ*DIMSZ], g_wq2[DIMSZ*DIMSZ];
__device__ __align__(16) __nv_bfloat16 g_wo0[DIMSZ*DIMSZ], g_wo1[DIMSZ*DIMSZ], g_wo2[DIMSZ*DIMSZ];

__device__ __forceinline__ float ex2(float x){float r;asm("ex2.approx.f32 %0,%1;":"=f"(r):"f"(x));return r;}
__device__ __forceinline__ u32 smem_u32(const void*p){u32 a;asm("{ .reg .u64 t; cvta.to.shared.u64 t,%1; cvt.u32.u64 %0,t; }":"=r"(a):"l"(p));return a;}
__device__ __forceinline__ u32 packbf(__nv_bfloat16 lo,__nv_bfloat16 hi){return (u32)__bfloat16_as_ushort(lo)|((u32)__bfloat16_as_ushort(hi)<<16);}
__device__ __forceinline__ void split3(float s,__nv_bfloat16&a,__nv_bfloat16&b,__nv_bfloat16&c){
    a=__float2bfloat16(s); float r=s-__bfloat162float(a);
    b=__float2bfloat16(r); c=__float2bfloat16(r-__bfloat162float(b));
}
__device__ __forceinline__ void ldmx4(u32* r,u32 a){
    asm volatile("ldmatrix.sync.aligned.m8n8.x4.shared.b16 {%0,%1,%2,%3},[%4];"
        :"=r"(r[0]),"=r"(r[1]),"=r"(r[2]),"=r"(r[3]):"r"(a));
}
__device__ __forceinline__ void mma16816(float* c,const u32* a,const u32* b){
    asm volatile("mma.sync.aligned.m16n8k16.row.col.f32.bf16.bf16.f32 "
        "{%0,%1,%2,%3},{%4,%5,%6,%7},{%8,%9},{%0,%1,%2,%3};"
        :"+f"(c[0]),"+f"(c[1]),"+f"(c[2]),"+f"(c[3])
        :"r"(a[0]),"r"(a[1]),"r"(a[2]),"r"(a[3]),"r"(b[0]),"r"(b[1]));
}

// ---------------- prep: generic fp32 -> 3 bf16-plane split ----------------
__global__ void split3_kernel(const float* __restrict__ src,
                              __nv_bfloat16* __restrict__ d0,__nv_bfloat16* __restrict__ d1,
                              __nv_bfloat16* __restrict__ d2){
    size_t i2=((size_t)blockIdx.x*256+threadIdx.x)*2;
    float2 v=*(const float2*)(src+i2);
    __nv_bfloat16 x0,x1,x2,y0,y1,y2;
    split3(v.x,x0,x1,x2); split3(v.y,y0,y1,y2);
    *(u32*)&d0[i2]=packbf(x0,y0);
    *(u32*)&d1[i2]=packbf(x1,y1);
    *(u32*)&d2[i2]=packbf(x2,y2);
}
__global__ void mem_split_kernel(const float* __restrict__ mem){
    int i=blockIdx.x*256+threadIdx.x;
    if(i>=MROWS*HD) return;
    int m=i>>6, d=i&63;
    float v=mem[i];
    __nv_bfloat16 b0,b1,b2; split3(v,b0,b1,b2);
    g_k0[i]=b0; g_k1[i]=b1; g_k2[i]=b2;
    g_vT0[d*MROWS+m]=b0; g_vT1[d*MROWS+m]=b1;
}

// ---------------- HMMA linear: C = A @ W^T + bias (6-product 3-way split) ----
// mode 0: write split3((acc+bias)*SCALE) -> g_q planes  (Wq path)
// mode 1: write (acc*INV_SCALE + bias) fp32 -> outp     (Wo path; inputs carry SCALE)
#define SMEM_LIN 98304
__global__ void __launch_bounds__(256,2)
linear_mma_kernel(const __nv_bfloat16* __restrict__ a0,const __nv_bfloat16* __restrict__ a1,
                  const __nv_bfloat16* __restrict__ a2,
                  const __nv_bfloat16* __restrict__ w0,const __nv_bfloat16* __restrict__ w1,
                  const __nv_bfloat16* __restrict__ w2,
                  const float* __restrict__ bias,float* __restrict__ outp,int mode){
    extern __shared__ char smc[];
    const u32 sb=smem_u32(smc);
    const int tid=threadIdx.x, wid=tid>>5, lane=tid&31;
    const int i0=blockIdx.y*128, j0=blockIdx.x*128;

    float sacc[16][4];
    #pragma unroll
    for(int n=0;n<16;n++){sacc[n][0]=0;sacc[n][1]=0;sacc[n][2]=0;sacc[n][3]=0;}

    const int arow=wid*16+(lane&15);
    const u32 arow128=(u32)(arow*128);
    const int arx=arow&7, acs=lane>>4;
    const int browB=((lane>>4)<<3)+(lane&7);
    const int kcB=(lane>>3)&1;

    for(int kc=0;kc<16;kc++){
        __syncthreads();
        { // load A splits + W splits (each 128x64) swizzled
            const __nv_bfloat16* ga[3]={a0,a1,a2};
            const __nv_bfloat16* gw[3]={w0,w1,w2};
            #pragma unroll
            for(int s=0;s<3;s++)
                #pragma unroll
                for(int j=0;j<4;j++){
                    int idx=tid+256*j, row=idx>>3, cc=idx&7;
                    u32 so=(u32)(row*128+((cc^(row&7))<<4));
                    *(uint4*)(smc+s*16384+so)
                        =*(const uint4*)(ga[s]+(size_t)(i0+row)*DIMSZ+kc*64+cc*8);
                    *(uint4*)(smc+49152+s*16384+so)
                        =*(const uint4*)(gw[s]+(size_t)(j0+row)*DIMSZ+kc*64+cc*8);
                }
        }
        __syncthreads();
        #pragma unroll
        for(int kt=0;kt<4;kt++){
            u32 aq[3][4];
            const u32 ca=arow128+(u32)(((kt*2+acs)^arx)<<4);
            ldmx4(aq[0],sb+ca);
            ldmx4(aq[1],sb+16384+ca);
            ldmx4(aq[2],sb+32768+ca);
            #pragma unroll
            for(int ntp=0;ntp<8;ntp++){
                const int rowB=ntp*16+browB;
                const u32 offB=(u32)(rowB*128)+(u32)(((kt*2+kcB)^(rowB&7))<<4);
                float* s0=sacc[2*ntp]; float* s1=sacc[2*ntp+1];
                u32 b[4];
                ldmx4(b,sb+49152+offB);
                mma16816(s0,aq[0],b);   mma16816(s0,aq[1],b);   mma16816(s0,aq[2],b);
                mma16816(s1,aq[0],b+2); mma16816(s1,aq[1],b+2); mma16816(s1,aq[2],b+2);
                ldmx4(b,sb+49152+16384+offB);
                mma16816(s0,aq[0],b);   mma16816(s0,aq[1],b);
                mma16816(s1,aq[0],b+2); mma16816(s1,aq[1],b+2);
                ldmx4(b,sb+49152+32768+offB);
                mma16816(s0,aq[0],b);
                mma16816(s1,aq[0],b+2);
            }
        }
    }

    // epilogue
    const int ra=i0+wid*16+(lane>>2), rb=ra+8;
    #pragma unroll
    for(int nt=0;nt<16;nt++){
        const int j=j0+nt*8+2*(lane&3);
        float2 bv=*(const float2*)(bias+j);
        if(mode==0){
            float v0=(sacc[nt][0]+bv.x)*SCALE_LOG2;
            float v1=(sacc[nt][1]+bv.y)*SCALE_LOG2;
            float v2=(sacc[nt][2]+bv.x)*SCALE_LOG2;
            float v3=(sacc[nt][3]+bv.y)*SCALE_LOG2;
            __nv_bfloat16 p0,p1,p2,q0,q1,q2;
            split3(v0,p0,p1,p2); split3(v1,q0,q1,q2);
            *(u32*)&g_q0[(size_t)ra*DIMSZ+j]=packbf(p0,q0);
            *(u32*)&g_q1[(size_t)ra*DIMSZ+j]=packbf(p1,q1);
            *(u32*)&g_q2[(size_t)ra*DIMSZ+j]=packbf(p2,q2);
            split3(v2,p0,p1,p2); split3(v3,q0,q1,q2);
            *(u32*)&g_q0[(size_t)rb*DIMSZ+j]=packbf(p0,q0);
            *(u32*)&g_q1[(size_t)rb*DIMSZ+j]=packbf(p1,q1);
            *(u32*)&g_q2[(size_t)rb*DIMSZ+j]=packbf(p2,q2);
        }else{
            *(float2*)(outp+(size_t)ra*DIMSZ+j)
                =make_float2(sacc[nt][0]*INV_SCALE+bv.x,sacc[nt][1]*INV_SCALE+bv.y);
            *(float2*)(outp+(size_t)rb*DIMSZ+j)
                =make_float2(sacc[nt][2]*INV_SCALE+bv.x,sacc[nt][3]*INV_SCALE+bv.y);
        }
    }
}

// ---------------- warp-mma flash Hopfield iteration (R10, unchanged) ----------------
#define OQ(s)  ((s)*16384)
#define OKS(s) (49152+(s)*8192)
#define OV(s)  (73728+(s)*8192)
#define SMEM_AT 90112

__global__ void __launch_bounds__(256,2)
hopfield_mma_kernel(float* __restrict__ dst){
    extern __shared__ char smc[];
    const u32 sb=smem_u32(smc);
    const int tid=threadIdx.x, wid=tid>>5, lane=tid&31;
    const int h=blockIdx.y, r0=blockIdx.x*128;

    { // load Q splits [128][64] swizzled
        const __nv_bfloat16* gq[3]={g_q0,g_q1,g_q2};
        #pragma unroll
        for(int s=0;s<3;s++)
            #pragma unroll
            for(int j=0;j<4;j++){
                int idx=tid+256*j, row=idx>>3, c=idx&7;
                *(uint4*)(smc+OQ(s)+row*128+((c^(row&7))<<4))
                    =*(const uint4*)(gq[s]+(size_t)(r0+row)*DIMSZ+h*HD+c*8);
            }
    }

    const int arow=wid*16+(lane&15);
    const u32 arow128=(u32)(arow*128);
    const int arx=arow&7, acs=lane>>4;
    const int browB=((lane>>4)<<3)+(lane&7);
    const int kcB=(lane>>3)&1;

    float ma=-1e30f,mb=-1e30f,la=0.0f,lb=0.0f;
    float oacc[8][4];
    #pragma unroll
    for(int i=0;i<8;i++){oacc[i][0]=0;oacc[i][1]=0;oacc[i][2]=0;oacc[i][3]=0;}

    for(int c=0;c<NCH;c++){
        __syncthreads();
        { // load K splits + Vt splits (each 64x64) swizzled
            const __nv_bfloat16* gk[3]={g_k0,g_k1,g_k2};
            #pragma unroll
            for(int s=0;s<3;s++)
                #pragma unroll
                for(int j=0;j<2;j++){
                    int idx=tid+256*j, row=idx>>3, cc=idx&7;
                    *(uint4*)(smc+OKS(s)+row*128+((cc^(row&7))<<4))
                        =*(const uint4*)(gk[s]+(size_t)(c*MC+row)*HD+cc*8);
                }
            const __nv_bfloat16* gv[2]={g_vT0,g_vT1};
            #pragma unroll
            for(int s=0;s<2;s++)
                #pragma unroll
                for(int j=0;j<2;j++){
                    int idx=tid+256*j, row=idx>>3, cc=idx&7;
                    *(uint4*)(smc+OV(s)+row*128+((cc^(row&7))<<4))
                        =*(const uint4*)(gv[s]+(size_t)row*MROWS+c*MC+cc*8);
                }
        }
        __syncthreads();

        float sacc[8][4];
        #pragma unroll
        for(int i=0;i<8;i++){sacc[i][0]=0;sacc[i][1]=0;sacc[i][2]=0;sacc[i][3]=0;}
        #pragma unroll
        for(int kt=0;kt<4;kt++){
            u32 aq[3][4];
            const u32 ca=arow128+(u32)(((kt*2+acs)^arx)<<4);
            ldmx4(aq[0],sb+OQ(0)+ca);
            ldmx4(aq[1],sb+OQ(1)+ca);
            ldmx4(aq[2],sb+OQ(2)+ca);
            #pragma unroll
            for(int ntp=0;ntp<4;ntp++){
                const int rowB=ntp*16+browB;
                const u32 offB=(u32)(rowB*128)+(u32)((((kt*2+kcB))^(rowB&7))<<4);
                u32 b0[4],b1[4],b2[4];
                ldmx4(b0,sb+OKS(0)+offB);
                ldmx4(b1,sb+OKS(1)+offB);
                ldmx4(b2,sb+OKS(2)+offB);
                float* s0=sacc[2*ntp]; float* s1=sacc[2*ntp+1];
                mma16816(s0,aq[0],b0);   mma16816(s0,aq[1],b0);   mma16816(s0,aq[2],b0);
                mma16816(s0,aq[0],b1);   mma16816(s0,aq[1],b1);   mma16816(s0,aq[0],b2);
                mma16816(s1,aq[0],b0+2); mma16816(s1,aq[1],b0+2); mma16816(s1,aq[2],b0+2);
                mma16816(s1,aq[0],b1+2); mma16816(s1,aq[1],b1+2); mma16816(s1,aq[0],b2+2);
            }
        }

        float mxa=-1e30f,mxb=-1e30f;
        #pragma unroll
        for(int nt=0;nt<8;nt++){
            mxa=fmaxf(mxa,fmaxf(sacc[nt][0],sacc[nt][1]));
            mxb=fmaxf(mxb,fmaxf(sacc[nt][2],sacc[nt][3]));
        }
        mxa=fmaxf(mxa,__shfl_xor_sync(0xffffffffu,mxa,1));
        mxa=fmaxf(mxa,__shfl_xor_sync(0xffffffffu,mxa,2));
        mxb=fmaxf(mxb,__shfl_xor_sync(0xffffffffu,mxb,1));
        mxb=fmaxf(mxb,__shfl_xor_sync(0xffffffffu,mxb,2));
        float mna=fmaxf(ma,mxa), mnb=fmaxf(mb,mxb);
        float ala=ex2(ma-mna), alb=ex2(mb-mnb);
        ma=mna; mb=mnb;
        float rsa=0.0f, rsb=0.0f;
        #pragma unroll
        for(int nt=0;nt<8;nt++){
            sacc[nt][0]=ex2(sacc[nt][0]-mna);
            sacc[nt][1]=ex2(sacc[nt][1]-mna);
            sacc[nt][2]=ex2(sacc[nt][2]-mnb);
            sacc[nt][3]=ex2(sacc[nt][3]-mnb);
            rsa+=sacc[nt][0]+sacc[nt][1];
            rsb+=sacc[nt][2]+sacc[nt][3];
        }
        rsa+=__shfl_xor_sync(0xffffffffu,rsa,1);
        rsa+=__shfl_xor_sync(0xffffffffu,rsa,2);
        rsb+=__shfl_xor_sync(0xffffffffu,rsb,1);
        rsb+=__shfl_xor_sync(0xffffffffu,rsb,2);
        la=la*ala+rsa; lb=lb*alb+rsb;
        #pragma unroll
        for(int dt=0;dt<8;dt++){
            oacc[dt][0]*=ala; oacc[dt][1]*=ala;
            oacc[dt][2]*=alb; oacc[dt][3]*=alb;
        }

        #pragma unroll
        for(int kt=0;kt<4;kt++){
            u32 ph[4], pl[4];
            #pragma unroll
            for(int half=0;half<2;half++){
                const int nt=2*kt+half;
                #pragma unroll
                for(int rr=0;rr<2;rr++){
                    float p0=sacc[nt][rr*2], p1=sacc[nt][rr*2+1];
                    __nv_bfloat16 h0=__float2bfloat16(p0), h1=__float2bfloat16(p1);
                    __nv_bfloat16 l0=__float2bfloat16(p0-__bfloat162float(h0));
                    __nv_bfloat16 l1=__float2bfloat16(p1-__bfloat162float(h1));
                    ph[half*2+rr]=packbf(h0,h1);
                    pl[half*2+rr]=packbf(l0,l1);
                }
            }
            #pragma unroll
            for(int dtp=0;dtp<4;dtp++){
                const int rowB=dtp*16+browB;
                const u32 offV=(u32)(rowB*128)+(u32)((((kt*2+kcB))^(rowB&7))<<4);
                u32 bv0[4],bv1[4];
                ldmx4(bv0,sb+OV(0)+offV);
                ldmx4(bv1,sb+OV(1)+offV);
                float* o0=oacc[2*dtp]; float* o1=oacc[2*dtp+1];
                mma16816(o0,ph,bv0);   mma16816(o0,pl,bv0);   mma16816(o0,ph,bv1);
                mma16816(o1,ph,bv0+2); mma16816(o1,pl,bv0+2); mma16816(o1,ph,bv1+2);
            }
        }
    }

    { // epilogue: normalize, store fp32 + next-stage Q splits
        const float inva=1.0f/la, invb=1.0f/lb;
        const int qa=r0+wid*16+(lane>>2), qb=qa+8;
        const size_t basea=(size_t)qa*DIMSZ+h*HD, baseb=(size_t)qb*DIMSZ+h*HD;
        #pragma unroll
        for(int dt=0;dt<8;dt++){
            const int d=dt*8+2*(lane&3);
            float v0=oacc[dt][0]*inva, v1=oacc[dt][1]*inva;
            float v2=oacc[dt][2]*invb, v3=oacc[dt][3]*invb;
            *(float2*)(dst+basea+d)=make_float2(v0,v1);
            *(float2*)(dst+baseb+d)=make_float2(v2,v3);
            __nv_bfloat16 x0,x1,x2,y0,y1,y2;
            split3(v0*SCALE_LOG2,x0,x1,x2); split3(v1*SCALE_LOG2,y0,y1,y2);
            *(u32*)&g_q0[basea+d]=packbf(x0,y0);
            *(u32*)&g_q1[basea+d]=packbf(x1,y1);
            *(u32*)&g_q2[basea+d]=packbf(x2,y2);
            split3(v2*SCALE_LOG2,x0,x1,x2); split3(v3*SCALE_LOG2,y0,y1,y2);
            *(u32*)&g_q0[baseb+d]=packbf(x0,y0);
            *(u32*)&g_q1[baseb+d]=packbf(x1,y1);
            *(u32*)&g_q2[baseb+d]=packbf(x2,y2);
        }
    }
}

extern "C" void kernel_launch(void* const* d_in, const int* in_sizes, int n_in,
                              void* d_out, int out_size){
    (void)in_sizes;(void)n_in;(void)out_size;
    const float* x=(const float*)d_in[0];
    const float* mem=(const float*)d_in[1];
    const float* Wq=(const float*)d_in[2];
    const float* bq=(const float*)d_in[3];
    const float* Wo=(const float*)d_in[4];
    const float* bo=(const float*)d_in[5];
    float* out=(float*)d_out;

    float *bufA=nullptr,*bufB=nullptr;
    cudaGetSymbolAddress((void**)&bufA,g_bufA);
    cudaGetSymbolAddress((void**)&bufB,g_bufB);
    __nv_bfloat16 *x0,*x1,*x2,*wq0,*wq1,*wq2,*wo0,*wo1,*wo2,*q0,*q1,*q2;
    cudaGetSymbolAddress((void**)&x0,g_x0);  cudaGetSymbolAddress((void**)&x1,g_x1);
    cudaGetSymbolAddress((void**)&x2,g_x2);
    cudaGetSymbolAddress((void**)&wq0,g_wq0);cudaGetSymbolAddress((void**)&wq1,g_wq1);
    cudaGetSymbolAddress((void**)&wq2,g_wq2);
    cudaGetSymbolAddress((void**)&wo0,g_wo0);cudaGetSymbolAddress((void**)&wo1,g_wo1);
    cudaGetSymbolAddress((void**)&wo2,g_wo2);
    cudaGetSymbolAddress((void**)&q0,g_q0);  cudaGetSymbolAddress((void**)&q1,g_q1);
    cudaGetSymbolAddress((void**)&q2,g_q2);

    cudaFuncSetAttribute(hopfield_mma_kernel,cudaFuncAttributeMaxDynamicSharedMemorySize,SMEM_AT);
    cudaFuncSetAttribute(linear_mma_kernel,cudaFuncAttributeMaxDynamicSharedMemorySize,SMEM_LIN);

    dim3 lg(DIMSZ/128,BL/128), ag(BL/128,NHEADS);

    mem_split_kernel<<<(MROWS*HD+255)/256,256>>>(mem);
    split3_kernel<<<(u32)((size_t)BL*DIMSZ/2/256),256>>>(x,x0,x1,x2);
    split3_kernel<<<DIMSZ*DIMSZ/2/256,256>>>(Wq,wq0,wq1,wq2);
    split3_kernel<<<DIMSZ*DIMSZ/2/256,256>>>(Wo,wo0,wo1,wo2);
    // q = x @ Wq^T + bq  -> scaled 3-plane splits (g_q*)
    linear_mma_kernel<<<lg,256,SMEM_LIN>>>(x0,x1,x2,wq0,wq1,wq2,bq,nullptr,0);
    // 2 Hopfield iterations (read g_q*, write g_q* for next stage)
    hopfield_mma_kernel<<<ag,256,SMEM_AT>>>(bufB);
    hopfield_mma_kernel<<<ag,256,SMEM_AT>>>(bufA);
    // out = q @ Wo^T + bo  (inputs carry SCALE; folded out in epilogue)
    linear_mma_kernel<<<lg,256,SMEM_LIN>>>(q0,q1,q2,wo0,wo1,wo2,bo,out,1);
}

// round 13
// speedup vs baseline: 2.7174x; 1.0655x over previous
#include <cuda_runtime.h>
#include <cuda_bf16.h>
#include <cstdint>
#include <cstddef>

#define DIMSZ 1024
#define HD 64
#define NHEADS 16
#define BL 4096
#define MROWS 2048
#define MC 64
#define NCH (MROWS/MC)
#define SCALE_LOG2 23.083120654223414f
#define INV_SCALE  (1.0f/SCALE_LOG2)

typedef unsigned long long ull;
typedef uint32_t u32;

__device__ float g_bufA[(size_t)BL*DIMSZ];
__device__ float g_bufB[(size_t)BL*DIMSZ];
__device__ __align__(16) __nv_bfloat16 g_k0[MROWS*HD], g_k1[MROWS*HD], g_k2[MROWS*HD];
__device__ __align__(16) __nv_bfloat16 g_vT0[HD*MROWS], g_vT1[HD*MROWS];
__device__ __align__(16) __nv_bfloat16 g_q0[(size_t)BL*DIMSZ], g_q1[(size_t)BL*DIMSZ], g_q2[(size_t)BL*DIMSZ];
__device__ __align__(16) __nv_bfloat16 g_x0[(size_t)BL*DIMSZ], g_x1[(size_t)BL*DIMSZ], g_x2[(size_t)BL*DIMSZ];
__device__ __align__(16) __nv_bfloat16 g_wq0[DIMSZ*DIMSZ], g_wq1[DIMSZ*DIMSZ], g_wq2[DIMSZ*DIMSZ];
__device__ __align__(16) __nv_bfloat16 g_wo0[DIMSZ*DIMSZ], g_wo1[DIMSZ*DIMSZ], g_wo2[DIMSZ*DIMSZ];

__device__ __forceinline__ float ex2(float x){float r;asm("ex2.approx.f32 %0,%1;":"=f"(r):"f"(x));return r;}
__device__ __forceinline__ u32 smem_u32(const void*p){u32 a;asm("{ .reg .u64 t; cvta.to.shared.u64 t,%1; cvt.u32.u64 %0,t; }":"=r"(a):"l"(p));return a;}
__device__ __forceinline__ u32 packbf(__nv_bfloat16 lo,__nv_bfloat16 hi){return (u32)__bfloat16_as_ushort(lo)|((u32)__bfloat16_as_ushort(hi)<<16);}
__device__ __forceinline__ void split3(float s,__nv_bfloat16&a,__nv_bfloat16&b,__nv_bfloat16&c){
    a=__float2bfloat16(s); float r=s-__bfloat162float(a);
    b=__float2bfloat16(r); c=__float2bfloat16(r-__bfloat162float(b));
}
__device__ __forceinline__ void ldmx4(u32* r,u32 a){
    asm volatile("ldmatrix.sync.aligned.m8n8.x4.shared.b16 {%0,%1,%2,%3},[%4];"
        :"=r"(r[0]),"=r"(r[1]),"=r"(r[2]),"=r"(r[3]):"r"(a));
}
__device__ __forceinline__ void mma16816(float* c,const u32* a,const u32* b){
    asm volatile("mma.sync.aligned.m16n8k16.row.col.f32.bf16.bf16.f32 "
        "{%0,%1,%2,%3},{%4,%5,%6,%7},{%8,%9},{%0,%1,%2,%3};"
        :"+f"(c[0]),"+f"(c[1]),"+f"(c[2]),"+f"(c[3])
        :"r"(a[0]),"r"(a[1]),"r"(a[2]),"r"(a[3]),"r"(b[0]),"r"(b[1]));
}
__device__ __forceinline__ void cpasync16(u32 dst,const void* src){
    asm volatile("cp.async.cg.shared.global [%0],[%1],16;"::"r"(dst),"l"(src));
}
#define CP_COMMIT() asm volatile("cp.async.commit_group;":::"memory")
#define CP_WAIT(n)  asm volatile("cp.async.wait_group %0;"::"n"(n):"memory")

// ---------------- prep: fp32 -> 3 bf16-plane splits ----------------
__global__ void split3_kernel(const float* __restrict__ src,
                              __nv_bfloat16* __restrict__ d0,__nv_bfloat16* __restrict__ d1,
                              __nv_bfloat16* __restrict__ d2){
    size_t i2=((size_t)blockIdx.x*256+threadIdx.x)*2;
    float2 v=*(const float2*)(src+i2);
    __nv_bfloat16 x0,x1,x2,y0,y1,y2;
    split3(v.x,x0,x1,x2); split3(v.y,y0,y1,y2);
    *(u32*)&d0[i2]=packbf(x0,y0);
    *(u32*)&d1[i2]=packbf(x1,y1);
    *(u32*)&d2[i2]=packbf(x2,y2);
}
__global__ void mem_split_kernel(const float* __restrict__ mem){
    int i=blockIdx.x*256+threadIdx.x;
    if(i>=MROWS*HD) return;
    int m=i>>6, d=i&63;
    float v=mem[i];
    __nv_bfloat16 b0,b1,b2; split3(v,b0,b1,b2);
    g_k0[i]=b0; g_k1[i]=b1; g_k2[i]=b2;
    g_vT0[d*MROWS+m]=b0; g_vT1[d*MROWS+m]=b1;
}

// ---------------- HMMA linear (R12-proven, unchanged) ----------------
#define SMEM_LIN 98304
__global__ void __launch_bounds__(256,2)
linear_mma_kernel(const __nv_bfloat16* __restrict__ a0,const __nv_bfloat16* __restrict__ a1,
                  const __nv_bfloat16* __restrict__ a2,
                  const __nv_bfloat16* __restrict__ w0,const __nv_bfloat16* __restrict__ w1,
                  const __nv_bfloat16* __restrict__ w2,
                  const float* __restrict__ bias,float* __restrict__ outp,int mode){
    extern __shared__ char smc[];
    const u32 sb=smem_u32(smc);
    const int tid=threadIdx.x, wid=tid>>5, lane=tid&31;
    const int i0=blockIdx.y*128, j0=blockIdx.x*128;

    float sacc[16][4];
    #pragma unroll
    for(int n=0;n<16;n++){sacc[n][0]=0;sacc[n][1]=0;sacc[n][2]=0;sacc[n][3]=0;}

    const int arow=wid*16+(lane&15);
    const u32 arow128=(u32)(arow*128);
    const int arx=arow&7, acs=lane>>4;
    const int browB=((lane>>4)<<3)+(lane&7);
    const int kcB=(lane>>3)&1;

    for(int kc=0;kc<16;kc++){
        __syncthreads();
        {
            const __nv_bfloat16* ga[3]={a0,a1,a2};
            const __nv_bfloat16* gw[3]={w0,w1,w2};
            #pragma unroll
            for(int s=0;s<3;s++)
                #pragma unroll
                for(int j=0;j<4;j++){
                    int idx=tid+256*j, row=idx>>3, cc=idx&7;
                    u32 so=(u32)(row*128+((cc^(row&7))<<4));
                    *(uint4*)(smc+s*16384+so)
                        =*(const uint4*)(ga[s]+(size_t)(i0+row)*DIMSZ+kc*64+cc*8);
                    *(uint4*)(smc+49152+s*16384+so)
                        =*(const uint4*)(gw[s]+(size_t)(j0+row)*DIMSZ+kc*64+cc*8);
                }
        }
        __syncthreads();
        #pragma unroll
        for(int kt=0;kt<4;kt++){
            u32 aq[3][4];
            const u32 ca=arow128+(u32)(((kt*2+acs)^arx)<<4);
            ldmx4(aq[0],sb+ca);
            ldmx4(aq[1],sb+16384+ca);
            ldmx4(aq[2],sb+32768+ca);
            #pragma unroll
            for(int ntp=0;ntp<8;ntp++){
                const int rowB=ntp*16+browB;
                const u32 offB=(u32)(rowB*128)+(u32)(((kt*2+kcB)^(rowB&7))<<4);
                float* s0=sacc[2*ntp]; float* s1=sacc[2*ntp+1];
                u32 b[4];
                ldmx4(b,sb+49152+offB);
                mma16816(s0,aq[0],b);   mma16816(s0,aq[1],b);   mma16816(s0,aq[2],b);
                mma16816(s1,aq[0],b+2); mma16816(s1,aq[1],b+2); mma16816(s1,aq[2],b+2);
                ldmx4(b,sb+49152+16384+offB);
                mma16816(s0,aq[0],b);   mma16816(s0,aq[1],b);
                mma16816(s1,aq[0],b+2); mma16816(s1,aq[1],b+2);
                ldmx4(b,sb+49152+32768+offB);
                mma16816(s0,aq[0],b);
                mma16816(s1,aq[0],b+2);
            }
        }
    }

    const int ra=i0+wid*16+(lane>>2), rb=ra+8;
    #pragma unroll
    for(int nt=0;nt<16;nt++){
        const int j=j0+nt*8+2*(lane&3);
        float2 bv=*(const float2*)(bias+j);
        if(mode==0){
            float v0=(sacc[nt][0]+bv.x)*SCALE_LOG2;
            float v1=(sacc[nt][1]+bv.y)*SCALE_LOG2;
            float v2=(sacc[nt][2]+bv.x)*SCALE_LOG2;
            float v3=(sacc[nt][3]+bv.y)*SCALE_LOG2;
            __nv_bfloat16 p0,p1,p2,q0,q1,q2;
            split3(v0,p0,p1,p2); split3(v1,q0,q1,q2);
            *(u32*)&g_q0[(size_t)ra*DIMSZ+j]=packbf(p0,q0);
            *(u32*)&g_q1[(size_t)ra*DIMSZ+j]=packbf(p1,q1);
            *(u32*)&g_q2[(size_t)ra*DIMSZ+j]=packbf(p2,q2);
            split3(v2,p0,p1,p2); split3(v3,q0,q1,q2);
            *(u32*)&g_q0[(size_t)rb*DIMSZ+j]=packbf(p0,q0);
            *(u32*)&g_q1[(size_t)rb*DIMSZ+j]=packbf(p1,q1);
            *(u32*)&g_q2[(size_t)rb*DIMSZ+j]=packbf(p2,q2);
        }else{
            *(float2*)(outp+(size_t)ra*DIMSZ+j)
                =make_float2(sacc[nt][0]*INV_SCALE+bv.x,sacc[nt][1]*INV_SCALE+bv.y);
            *(float2*)(outp+(size_t)rb*DIMSZ+j)
                =make_float2(sacc[nt][2]*INV_SCALE+bv.x,sacc[nt][3]*INV_SCALE+bv.y);
        }
    }
}

// ---------------- warp-mma flash Hopfield: Qregs + cp.async double-buffer ----------------
// smem: BUF(b)=b*40960 {K0,K1,K2,V0,V1 tiles of 8192B}, Q2 @81920 (16KB)
#define BUFO(b) ((b)*40960)
#define Q2O 81920
#define SMEM_AT 98304

__global__ void __launch_bounds__(256,2)
hopfield_mma_kernel(float* __restrict__ dst){
    extern __shared__ char smc[];
    const u32 sb=smem_u32(smc);
    const int tid=threadIdx.x, wid=tid>>5, lane=tid&31;
    const int h=blockIdx.y, r0=blockIdx.x*128;

    const int arow=wid*16+(lane&15);
    const u32 arow128=(u32)(arow*128);
    const int arx=arow&7, acs=lane>>4;
    const int browB=((lane>>4)<<3)+(lane&7);
    const int kcB=(lane>>3)&1;

    // ---- stage q0,q1 through BUF(0), hold A-fragments in registers ----
    u32 aq0[4][4], aq1[4][4];
    #pragma unroll
    for(int j=0;j<4;j++){
        int idx=tid+256*j, row=idx>>3, c=idx&7;
        *(uint4*)(smc+row*128+((c^(row&7))<<4))
            =*(const uint4*)(g_q0+(size_t)(r0+row)*DIMSZ+h*HD+c*8);
    }
    __syncthreads();
    #pragma unroll
    for(int kt=0;kt<4;kt++) ldmx4(aq0[kt],sb+arow128+(u32)(((kt*2+acs)^arx)<<4));
    __syncthreads();
    #pragma unroll
    for(int j=0;j<4;j++){
        int idx=tid+256*j, row=idx>>3, c=idx&7;
        *(uint4*)(smc+row*128+((c^(row&7))<<4))
            =*(const uint4*)(g_q1+(size_t)(r0+row)*DIMSZ+h*HD+c*8);
    }
    __syncthreads();
    #pragma unroll
    for(int kt=0;kt<4;kt++) ldmx4(aq1[kt],sb+arow128+(u32)(((kt*2+acs)^arx)<<4));
    __syncthreads();
    // q2 into its permanent region (visible after first loop sync)
    #pragma unroll
    for(int j=0;j<4;j++){
        int idx=tid+256*j, row=idx>>3, c=idx&7;
        *(uint4*)(smc+Q2O+row*128+((c^(row&7))<<4))
            =*(const uint4*)(g_q2+(size_t)(r0+row)*DIMSZ+h*HD+c*8);
    }

    // loader lambda: issue cp.async for chunk c into buffer b
    auto issue=[&](int c,u32 bofs){
        const __nv_bfloat16* gk[3]={g_k0,g_k1,g_k2};
        #pragma unroll
        for(int s=0;s<3;s++)
            #pragma unroll
            for(int j=0;j<2;j++){
                int idx=tid+256*j, row=idx>>3, cc=idx&7;
                cpasync16(sb+bofs+(u32)(s*8192+row*128+((cc^(row&7))<<4)),
                          gk[s]+(size_t)(c*MC+row)*HD+cc*8);
            }
        const __nv_bfloat16* gv[2]={g_vT0,g_vT1};
        #pragma unroll
        for(int s=0;s<2;s++)
            #pragma unroll
            for(int j=0;j<2;j++){
                int idx=tid+256*j, row=idx>>3, cc=idx&7;
                cpasync16(sb+bofs+(u32)(24576+s*8192+row*128+((cc^(row&7))<<4)),
                          gv[s]+(size_t)row*MROWS+c*MC+cc*8);
            }
    };

    float ma=-1e30f,mb=-1e30f,la=0.0f,lb=0.0f;
    float oacc[8][4];
    #pragma unroll
    for(int i=0;i<8;i++){oacc[i][0]=0;oacc[i][1]=0;oacc[i][2]=0;oacc[i][3]=0;}

    // prologue: chunk 0 in flight
    issue(0,BUFO(0));
    CP_COMMIT();

    for(int c=0;c<NCH;c++){
        if(c+1<NCH){ issue(c+1,BUFO((c+1)&1)); CP_COMMIT(); CP_WAIT(1); }
        else CP_WAIT(0);
        __syncthreads();                       // buf[c&1] + q2 visible

        const u32 kb=sb+BUFO(c&1);

        // ---- S = Q@K^T, 6 split products ----
        float sacc[8][4];
        #pragma unroll
        for(int i=0;i<8;i++){sacc[i][0]=0;sacc[i][1]=0;sacc[i][2]=0;sacc[i][3]=0;}
        #pragma unroll
        for(int kt=0;kt<4;kt++){
            u32 aq2[4];
            const u32 ca=(u32)(((kt*2+acs)^arx)<<4);
            ldmx4(aq2,sb+Q2O+arow128+ca);
            #pragma unroll
            for(int ntp=0;ntp<4;ntp++){
                const int rowB=ntp*16+browB;
                const u32 offB=(u32)(rowB*128)+(u32)((((kt*2+kcB))^(rowB&7))<<4);
                u32 b0[4],b1[4],b2[4];
                ldmx4(b0,kb+offB);
                ldmx4(b1,kb+8192+offB);
                ldmx4(b2,kb+16384+offB);
                float* s0=sacc[2*ntp]; float* s1=sacc[2*ntp+1];
                mma16816(s0,aq0[kt],b0);   mma16816(s0,aq1[kt],b0);   mma16816(s0,aq2,b0);
                mma16816(s0,aq0[kt],b1);   mma16816(s0,aq1[kt],b1);   mma16816(s0,aq0[kt],b2);
                mma16816(s1,aq0[kt],b0+2); mma16816(s1,aq1[kt],b0+2); mma16816(s1,aq2,b0+2);
                mma16816(s1,aq0[kt],b1+2); mma16816(s1,aq1[kt],b1+2); mma16816(s1,aq0[kt],b2+2);
            }
        }

        // ---- online softmax (base 2) ----
        float mxa=-1e30f,mxb=-1e30f;
        #pragma unroll
        for(int nt=0;nt<8;nt++){
            mxa=fmaxf(mxa,fmaxf(sacc[nt][0],sacc[nt][1]));
            mxb=fmaxf(mxb,fmaxf(sacc[nt][2],sacc[nt][3]));
        }
        mxa=fmaxf(mxa,__shfl_xor_sync(0xffffffffu,mxa,1));
        mxa=fmaxf(mxa,__shfl_xor_sync(0xffffffffu,mxa,2));
        mxb=fmaxf(mxb,__shfl_xor_sync(0xffffffffu,mxb,1));
        mxb=fmaxf(mxb,__shfl_xor_sync(0xffffffffu,mxb,2));
        float mna=fmaxf(ma,mxa), mnb=fmaxf(mb,mxb);
        float ala=ex2(ma-mna), alb=ex2(mb-mnb);
        ma=mna; mb=mnb;
        float rsa=0.0f, rsb=0.0f;
        #pragma unroll
        for(int nt=0;nt<8;nt++){
            sacc[nt][0]=ex2(sacc[nt][0]-mna);
            sacc[nt][1]=ex2(sacc[nt][1]-mna);
            sacc[nt][2]=ex2(sacc[nt][2]-mnb);
            sacc[nt][3]=ex2(sacc[nt][3]-mnb);
            rsa+=sacc[nt][0]+sacc[nt][1];
            rsb+=sacc[nt][2]+sacc[nt][3];
        }
        rsa+=__shfl_xor_sync(0xffffffffu,rsa,1);
        rsa+=__shfl_xor_sync(0xffffffffu,rsa,2);
        rsb+=__shfl_xor_sync(0xffffffffu,rsb,1);
        rsb+=__shfl_xor_sync(0xffffffffu,rsb,2);
        la=la*ala+rsa; lb=lb*alb+rsb;
        #pragma unroll
        for(int dt=0;dt<8;dt++){
            oacc[dt][0]*=ala; oacc[dt][1]*=ala;
            oacc[dt][2]*=alb; oacc[dt][3]*=alb;
        }

        // ---- PV per kt ----
        #pragma unroll
        for(int kt=0;kt<4;kt++){
            u32 ph[4], pl[4];
            #pragma unroll
            for(int half=0;half<2;half++){
                const int nt=2*kt+half;
                #pragma unroll
                for(int rr=0;rr<2;rr++){
                    float p0=sacc[nt][rr*2], p1=sacc[nt][rr*2+1];
                    __nv_bfloat16 h0=__float2bfloat16(p0), h1=__float2bfloat16(p1);
                    __nv_bfloat16 l0=__float2bfloat16(p0-__bfloat162float(h0));
                    __nv_bfloat16 l1=__float2bfloat16(p1-__bfloat162float(h1));
                    ph[half*2+rr]=packbf(h0,h1);
                    pl[half*2+rr]=packbf(l0,l1);
                }
            }
            #pragma unroll
            for(int dtp=0;dtp<4;dtp++){
                const int rowB=dtp*16+browB;
                const u32 offV=(u32)(rowB*128)+(u32)((((kt*2+kcB))^(rowB&7))<<4);
                u32 bv0[4],bv1[4];
                ldmx4(bv0,kb+24576+offV);
                ldmx4(bv1,kb+32768+offV);
                float* o0=oacc[2*dtp]; float* o1=oacc[2*dtp+1];
                mma16816(o0,ph,bv0);   mma16816(o0,pl,bv0);   mma16816(o0,ph,bv1);
                mma16816(o1,ph,bv0+2); mma16816(o1,pl,bv0+2); mma16816(o1,ph,bv1+2);
            }
        }
        __syncthreads();                       // reads of buf[(c+1)&1] (prev chunk) done
    }

    { // epilogue: normalize, store fp32 + next-stage Q splits
        const float inva=1.0f/la, invb=1.0f/lb;
        const int qa=r0+wid*16+(lane>>2), qb=qa+8;
        const size_t basea=(size_t)qa*DIMSZ+h*HD, baseb=(size_t)qb*DIMSZ+h*HD;
        #pragma unroll
        for(int dt=0;dt<8;dt++){
            const int d=dt*8+2*(lane&3);
            float v0=oacc[dt][0]*inva, v1=oacc[dt][1]*inva;
            float v2=oacc[dt][2]*invb, v3=oacc[dt][3]*invb;
            *(float2*)(dst+basea+d)=make_float2(v0,v1);
            *(float2*)(dst+baseb+d)=make_float2(v2,v3);
            __nv_bfloat16 x0,x1,x2,y0,y1,y2;
            split3(v0*SCALE_LOG2,x0,x1,x2); split3(v1*SCALE_LOG2,y0,y1,y2);
            *(u32*)&g_q0[basea+d]=packbf(x0,y0);
            *(u32*)&g_q1[basea+d]=packbf(x1,y1);
            *(u32*)&g_q2[basea+d]=packbf(x2,y2);
            split3(v2*SCALE_LOG2,x0,x1,x2); split3(v3*SCALE_LOG2,y0,y1,y2);
            *(u32*)&g_q0[baseb+d]=packbf(x0,y0);
            *(u32*)&g_q1[baseb+d]=packbf(x1,y1);
            *(u32*)&g_q2[baseb+d]=packbf(x2,y2);
        }
    }
}

extern "C" void kernel_launch(void* const* d_in, const int* in_sizes, int n_in,
                              void* d_out, int out_size){
    (void)in_sizes;(void)n_in;(void)out_size;
    const float* x=(const float*)d_in[0];
    const float* mem=(const float*)d_in[1];
    const float* Wq=(const float*)d_in[2];
    const float* bq=(const float*)d_in[3];
    const float* Wo=(const float*)d_in[4];
    const float* bo=(const float*)d_in[5];
    float* out=(float*)d_out;

    float *bufA=nullptr,*bufB=nullptr;
    cudaGetSymbolAddress((void**)&bufA,g_bufA);
    cudaGetSymbolAddress((void**)&bufB,g_bufB);
    __nv_bfloat16 *x0,*x1,*x2,*wq0,*wq1,*wq2,*wo0,*wo1,*wo2,*q0,*q1,*q2;
    cudaGetSymbolAddress((void**)&x0,g_x0);  cudaGetSymbolAddress((void**)&x1,g_x1);
    cudaGetSymbolAddress((void**)&x2,g_x2);
    cudaGetSymbolAddress((void**)&wq0,g_wq0);cudaGetSymbolAddress((void**)&wq1,g_wq1);
    cudaGetSymbolAddress((void**)&wq2,g_wq2);
    cudaGetSymbolAddress((void**)&wo0,g_wo0);cudaGetSymbolAddress((void**)&wo1,g_wo1);
    cudaGetSymbolAddress((void**)&wo2,g_wo2);
    cudaGetSymbolAddress((void**)&q0,g_q0);  cudaGetSymbolAddress((void**)&q1,g_q1);
    cudaGetSymbolAddress((void**)&q2,g_q2);

    cudaFuncSetAttribute(hopfield_mma_kernel,cudaFuncAttributeMaxDynamicSharedMemorySize,SMEM_AT);
    cudaFuncSetAttribute(linear_mma_kernel,cudaFuncAttributeMaxDynamicSharedMemorySize,SMEM_LIN);

    dim3 lg(DIMSZ/128,BL/128), ag(BL/128,NHEADS);

    mem_split_kernel<<<(MROWS*HD+255)/256,256>>>(mem);
    split3_kernel<<<(u32)((size_t)BL*DIMSZ/2/256),256>>>(x,x0,x1,x2);
    split3_kernel<<<DIMSZ*DIMSZ/2/256,256>>>(Wq,wq0,wq1,wq2);
    split3_kernel<<<DIMSZ*DIMSZ/2/256,256>>>(Wo,wo0,wo1,wo2);
    linear_mma_kernel<<<lg,256,SMEM_LIN>>>(x0,x1,x2,wq0,wq1,wq2,bq,nullptr,0);
    hopfield_mma_kernel<<<ag,256,SMEM_AT>>>(bufB);
    hopfield_mma_kernel<<<ag,256,SMEM_AT>>>(bufA);
    linear_mma_kernel<<<lg,256,SMEM_LIN>>>(q0,q1,q2,wo0,wo1,wo2,bo,out,1);
}

// round 14
// speedup vs baseline: 3.6110x; 1.3289x over previous
#include <cuda_runtime.h>
#include <cuda_fp16.h>
#include <cstdint>
#include <cstddef>

#define DIMSZ 1024
#define HD 64
#define NHEADS 16
#define BL 4096
#define MROWS 2048
#define MC 64
#define NCH (MROWS/MC)
#define SCALE_LOG2 23.083120654223414f
#define INV_SCALE  (1.0f/SCALE_LOG2)

typedef uint32_t u32;

// fp16 planes (no allocations allowed)
__device__ __align__(16) __half g_k0[MROWS*HD], g_k1[MROWS*HD];
__device__ __align__(16) __half g_vT0[HD*MROWS], g_vT1[HD*MROWS];
__device__ __align__(16) __half g_q0[(size_t)BL*DIMSZ], g_q1[(size_t)BL*DIMSZ];
__device__ __align__(16) __half g_x0[(size_t)BL*DIMSZ], g_x1[(size_t)BL*DIMSZ], g_x2[(size_t)BL*DIMSZ];
__device__ __align__(16) __half g_wq0[DIMSZ*DIMSZ], g_wq1[DIMSZ*DIMSZ], g_wq2[DIMSZ*DIMSZ];
__device__ __align__(16) __half g_wo0[DIMSZ*DIMSZ], g_wo1[DIMSZ*DIMSZ];

__device__ __forceinline__ float ex2(float x){float r;asm("ex2.approx.f32 %0,%1;":"=f"(r):"f"(x));return r;}
__device__ __forceinline__ u32 smem_u32(const void*p){u32 a;asm("{ .reg .u64 t; cvta.to.shared.u64 t,%1; cvt.u32.u64 %0,t; }":"=r"(a):"l"(p));return a;}
__device__ __forceinline__ u32 packh(__half lo,__half hi){return (u32)__half_as_ushort(lo)|((u32)__half_as_ushort(hi)<<16);}
__device__ __forceinline__ void split2h(float s,__half&a,__half&b){
    a=__float2half_rn(s); b=__float2half_rn(s-__half2float(a));
}
__device__ __forceinline__ void split3h(float s,__half&a,__half&b,__half&c){
    a=__float2half_rn(s); float r=s-__half2float(a);
    b=__float2half_rn(r); c=__float2half_rn(r-__half2float(b));
}
__device__ __forceinline__ void ldmx4(u32* r,u32 a){
    asm volatile("ldmatrix.sync.aligned.m8n8.x4.shared.b16 {%0,%1,%2,%3},[%4];"
        :"=r"(r[0]),"=r"(r[1]),"=r"(r[2]),"=r"(r[3]):"r"(a));
}
__device__ __forceinline__ void mma16816(float* c,const u32* a,const u32* b){
    asm volatile("mma.sync.aligned.m16n8k16.row.col.f32.f16.f16.f32 "
        "{%0,%1,%2,%3},{%4,%5,%6,%7},{%8,%9},{%0,%1,%2,%3};"
        :"+f"(c[0]),"+f"(c[1]),"+f"(c[2]),"+f"(c[3])
        :"r"(a[0]),"r"(a[1]),"r"(a[2]),"r"(a[3]),"r"(b[0]),"r"(b[1]));
}
__device__ __forceinline__ void cpasync16(u32 dst,const void* src){
    asm volatile("cp.async.cg.shared.global [%0],[%1],16;"::"r"(dst),"l"(src));
}
#define CP_COMMIT() asm volatile("cp.async.commit_group;":::"memory")
#define CP_WAIT(n)  asm volatile("cp.async.wait_group %0;"::"n"(n):"memory")

// ---------------- prep kernels ----------------
__global__ void split3h_kernel(const float* __restrict__ src,
                               __half* __restrict__ d0,__half* __restrict__ d1,
                               __half* __restrict__ d2){
    size_t i2=((size_t)blockIdx.x*256+threadIdx.x)*2;
    float2 v=*(const float2*)(src+i2);
    __half x0,x1,x2,y0,y1,y2;
    split3h(v.x,x0,x1,x2); split3h(v.y,y0,y1,y2);
    *(u32*)&d0[i2]=packh(x0,y0);
    *(u32*)&d1[i2]=packh(x1,y1);
    *(u32*)&d2[i2]=packh(x2,y2);
}
__global__ void split2h_kernel(const float* __restrict__ src,
                               __half* __restrict__ d0,__half* __restrict__ d1){
    size_t i2=((size_t)blockIdx.x*256+threadIdx.x)*2;
    float2 v=*(const float2*)(src+i2);
    __half x0,x1,y0,y1;
    split2h(v.x,x0,x1); split2h(v.y,y0,y1);
    *(u32*)&d0[i2]=packh(x0,y0);
    *(u32*)&d1[i2]=packh(x1,y1);
}
__global__ void mem_split_kernel(const float* __restrict__ mem){
    int i=blockIdx.x*256+threadIdx.x;
    if(i>=MROWS*HD) return;
    int m=i>>6, d=i&63;
    __half b0,b1; split2h(mem[i],b0,b1);
    g_k0[i]=b0; g_k1[i]=b1;
    g_vT0[d*MROWS+m]=b0; g_vT1[d*MROWS+m]=b1;
}

// ---------------- Wq linear: 3-plane x 3-plane, 6 products (near-exact) ----------------
// out: split2h((acc+bias)*SCALE) -> g_q0,g_q1
#define SMEM_L6 98304
__global__ void __launch_bounds__(256,2)
linear6_kernel(const __half* __restrict__ a0,const __half* __restrict__ a1,
               const __half* __restrict__ a2,
               const __half* __restrict__ w0,const __half* __restrict__ w1,
               const __half* __restrict__ w2,
               const float* __restrict__ bias){
    extern __shared__ char smc[];
    const u32 sb=smem_u32(smc);
    const int tid=threadIdx.x, wid=tid>>5, lane=tid&31;
    const int i0=blockIdx.y*128, j0=blockIdx.x*128;

    float sacc[16][4];
    #pragma unroll
    for(int n=0;n<16;n++){sacc[n][0]=0;sacc[n][1]=0;sacc[n][2]=0;sacc[n][3]=0;}

    const int arow=wid*16+(lane&15);
    const u32 arow128=(u32)(arow*128);
    const int arx=arow&7, acs=lane>>4;
    const int browB=((lane>>4)<<3)+(lane&7);
    const int kcB=(lane>>3)&1;

    for(int kc=0;kc<16;kc++){
        __syncthreads();
        {
            const __half* ga[3]={a0,a1,a2};
            const __half* gw[3]={w0,w1,w2};
            #pragma unroll
            for(int s=0;s<3;s++)
                #pragma unroll
                for(int j=0;j<4;j++){
                    int idx=tid+256*j, row=idx>>3, cc=idx&7;
                    u32 so=(u32)(row*128+((cc^(row&7))<<4));
                    *(uint4*)(smc+s*16384+so)
                        =*(const uint4*)(ga[s]+(size_t)(i0+row)*DIMSZ+kc*64+cc*8);
                    *(uint4*)(smc+49152+s*16384+so)
                        =*(const uint4*)(gw[s]+(size_t)(j0+row)*DIMSZ+kc*64+cc*8);
                }
        }
        __syncthreads();
        #pragma unroll
        for(int kt=0;kt<4;kt++){
            u32 aq[3][4];
            const u32 ca=arow128+(u32)(((kt*2+acs)^arx)<<4);
            ldmx4(aq[0],sb+ca);
            ldmx4(aq[1],sb+16384+ca);
            ldmx4(aq[2],sb+32768+ca);
            #pragma unroll
            for(int ntp=0;ntp<8;ntp++){
                const int rowB=ntp*16+browB;
                const u32 offB=(u32)(rowB*128)+(u32)(((kt*2+kcB)^(rowB&7))<<4);
                float* s0=sacc[2*ntp]; float* s1=sacc[2*ntp+1];
                u32 b[4];
                ldmx4(b,sb+49152+offB);
                mma16816(s0,aq[0],b);   mma16816(s0,aq[1],b);   mma16816(s0,aq[2],b);
                mma16816(s1,aq[0],b+2); mma16816(s1,aq[1],b+2); mma16816(s1,aq[2],b+2);
                ldmx4(b,sb+49152+16384+offB);
                mma16816(s0,aq[0],b);   mma16816(s0,aq[1],b);
                mma16816(s1,aq[0],b+2); mma16816(s1,aq[1],b+2);
                ldmx4(b,sb+49152+32768+offB);
                mma16816(s0,aq[0],b);
                mma16816(s1,aq[0],b+2);
            }
        }
    }

    const int ra=i0+wid*16+(lane>>2), rb=ra+8;
    #pragma unroll
    for(int nt=0;nt<16;nt++){
        const int j=j0+nt*8+2*(lane&3);
        float2 bv=*(const float2*)(bias+j);
        float v0=(sacc[nt][0]+bv.x)*SCALE_LOG2;
        float v1=(sacc[nt][1]+bv.y)*SCALE_LOG2;
        float v2=(sacc[nt][2]+bv.x)*SCALE_LOG2;
        float v3=(sacc[nt][3]+bv.y)*SCALE_LOG2;
        __half p0,p1,q0,q1;
        split2h(v0,p0,p1); split2h(v1,q0,q1);
        *(u32*)&g_q0[(size_t)ra*DIMSZ+j]=packh(p0,q0);
        *(u32*)&g_q1[(size_t)ra*DIMSZ+j]=packh(p1,q1);
        split2h(v2,p0,p1); split2h(v3,q0,q1);
        *(u32*)&g_q0[(size_t)rb*DIMSZ+j]=packh(p0,q0);
        *(u32*)&g_q1[(size_t)rb*DIMSZ+j]=packh(p1,q1);
    }
}

// ---------------- Wo linear: 2-plane x 2-plane, 3 products ----------------
#define SMEM_L3 65536
__global__ void __launch_bounds__(256,2)
linear3_kernel(const __half* __restrict__ a0,const __half* __restrict__ a1,
               const __half* __restrict__ w0,const __half* __restrict__ w1,
               const float* __restrict__ bias,float* __restrict__ outp){
    extern __shared__ char smc[];
    const u32 sb=smem_u32(smc);
    const int tid=threadIdx.x, wid=tid>>5, lane=tid&31;
    const int i0=blockIdx.y*128, j0=blockIdx.x*128;

    float sacc[16][4];
    #pragma unroll
    for(int n=0;n<16;n++){sacc[n][0]=0;sacc[n][1]=0;sacc[n][2]=0;sacc[n][3]=0;}

    const int arow=wid*16+(lane&15);
    const u32 arow128=(u32)(arow*128);
    const int arx=arow&7, acs=lane>>4;
    const int browB=((lane>>4)<<3)+(lane&7);
    const int kcB=(lane>>3)&1;

    for(int kc=0;kc<16;kc++){
        __syncthreads();
        {
            const __half* ga[2]={a0,a1};
            const __half* gw[2]={w0,w1};
            #pragma unroll
            for(int s=0;s<2;s++)
                #pragma unroll
                for(int j=0;j<4;j++){
                    int idx=tid+256*j, row=idx>>3, cc=idx&7;
                    u32 so=(u32)(row*128+((cc^(row&7))<<4));
                    *(uint4*)(smc+s*16384+so)
                        =*(const uint4*)(ga[s]+(size_t)(i0+row)*DIMSZ+kc*64+cc*8);
                    *(uint4*)(smc+32768+s*16384+so)
                        =*(const uint4*)(gw[s]+(size_t)(j0+row)*DIMSZ+kc*64+cc*8);
                }
        }
        __syncthreads();
        #pragma unroll
        for(int kt=0;kt<4;kt++){
            u32 aq[2][4];
            const u32 ca=arow128+(u32)(((kt*2+acs)^arx)<<4);
            ldmx4(aq[0],sb+ca);
            ldmx4(aq[1],sb+16384+ca);
            #pragma unroll
            for(int ntp=0;ntp<8;ntp++){
                const int rowB=ntp*16+browB;
                const u32 offB=(u32)(rowB*128)+(u32)(((kt*2+kcB)^(rowB&7))<<4);
                float* s0=sacc[2*ntp]; float* s1=sacc[2*ntp+1];
                u32 bh[4],bl[4];
                ldmx4(bh,sb+32768+offB);
                ldmx4(bl,sb+49152+offB);
                mma16816(s0,aq[0],bh);   mma16816(s0,aq[1],bh);   mma16816(s0,aq[0],bl);
                mma16816(s1,aq[0],bh+2); mma16816(s1,aq[1],bh+2); mma16816(s1,aq[0],bl+2);
            }
        }
    }

    const int ra=i0+wid*16+(lane>>2), rb=ra+8;
    #pragma unroll
    for(int nt=0;nt<16;nt++){
        const int j=j0+nt*8+2*(lane&3);
        float2 bv=*(const float2*)(bias+j);
        *(float2*)(outp+(size_t)ra*DIMSZ+j)
            =make_float2(sacc[nt][0]*INV_SCALE+bv.x,sacc[nt][1]*INV_SCALE+bv.y);
        *(float2*)(outp+(size_t)rb*DIMSZ+j)
            =make_float2(sacc[nt][2]*INV_SCALE+bv.x,sacc[nt][3]*INV_SCALE+bv.y);
    }
}

// ---------------- attention: fp16 2-way, Qregs + cp.async double-buffer ----------------
// BUF(b)=b*32768 {K0@0,K1@8192,V0@16384,V1@24576}; SMEM_AT=65536
#define BUFO(b) ((b)*32768)
#define SMEM_AT 65536

__global__ void __launch_bounds__(256,2)
hopfield_mma_kernel(){
    extern __shared__ char smc[];
    const u32 sb=smem_u32(smc);
    const int tid=threadIdx.x, wid=tid>>5, lane=tid&31;
    const int h=blockIdx.y, r0=blockIdx.x*128;

    const int arow=wid*16+(lane&15);
    const u32 arow128=(u32)(arow*128);
    const int arx=arow&7, acs=lane>>4;
    const int browB=((lane>>4)<<3)+(lane&7);
    const int kcB=(lane>>3)&1;

    // ---- stage q0,q1 through BUF(0), hold A-fragments in registers ----
    u32 aqh[4][4], aql[4][4];
    #pragma unroll
    for(int j=0;j<4;j++){
        int idx=tid+256*j, row=idx>>3, c=idx&7;
        *(uint4*)(smc+row*128+((c^(row&7))<<4))
            =*(const uint4*)(g_q0+(size_t)(r0+row)*DIMSZ+h*HD+c*8);
    }
    __syncthreads();
    #pragma unroll
    for(int kt=0;kt<4;kt++) ldmx4(aqh[kt],sb+arow128+(u32)(((kt*2+acs)^arx)<<4));
    __syncthreads();
    #pragma unroll
    for(int j=0;j<4;j++){
        int idx=tid+256*j, row=idx>>3, c=idx&7;
        *(uint4*)(smc+row*128+((c^(row&7))<<4))
            =*(const uint4*)(g_q1+(size_t)(r0+row)*DIMSZ+h*HD+c*8);
    }
    __syncthreads();
    #pragma unroll
    for(int kt=0;kt<4;kt++) ldmx4(aql[kt],sb+arow128+(u32)(((kt*2+acs)^arx)<<4));
    __syncthreads();

    auto issue=[&](int c,u32 bofs){
        const __half* gk[2]={g_k0,g_k1};
        #pragma unroll
        for(int s=0;s<2;s++)
            #pragma unroll
            for(int j=0;j<2;j++){
                int idx=tid+256*j, row=idx>>3, cc=idx&7;
                cpasync16(sb+bofs+(u32)(s*8192+row*128+((cc^(row&7))<<4)),
                          gk[s]+(size_t)(c*MC+row)*HD+cc*8);
            }
        const __half* gv[2]={g_vT0,g_vT1};
        #pragma unroll
        for(int s=0;s<2;s++)
            #pragma unroll
            for(int j=0;j<2;j++){
                int idx=tid+256*j, row=idx>>3, cc=idx&7;
                cpasync16(sb+bofs+(u32)(16384+s*8192+row*128+((cc^(row&7))<<4)),
                          gv[s]+(size_t)row*MROWS+c*MC+cc*8);
            }
    };

    float ma=-1e30f,mb=-1e30f,la=0.0f,lb=0.0f;
    float oacc[8][4];
    #pragma unroll
    for(int i=0;i<8;i++){oacc[i][0]=0;oacc[i][1]=0;oacc[i][2]=0;oacc[i][3]=0;}

    issue(0,BUFO(0));
    CP_COMMIT();

    for(int c=0;c<NCH;c++){
        if(c+1<NCH){ issue(c+1,BUFO((c+1)&1)); CP_COMMIT(); CP_WAIT(1); }
        else CP_WAIT(0);
        __syncthreads();

        const u32 kb=sb+BUFO(c&1);

        // ---- S = Q@K^T, fp16 2-way: hh + lh + hl ----
        float sacc[8][4];
        #pragma unroll
        for(int i=0;i<8;i++){sacc[i][0]=0;sacc[i][1]=0;sacc[i][2]=0;sacc[i][3]=0;}
        #pragma unroll
        for(int kt=0;kt<4;kt++){
            #pragma unroll
            for(int ntp=0;ntp<4;ntp++){
                const int rowB=ntp*16+browB;
                const u32 offB=(u32)(rowB*128)+(u32)((((kt*2+kcB))^(rowB&7))<<4);
                u32 bh[4],bl[4];
                ldmx4(bh,kb+offB);
                ldmx4(bl,kb+8192+offB);
                float* s0=sacc[2*ntp]; float* s1=sacc[2*ntp+1];
                mma16816(s0,aqh[kt],bh);   mma16816(s0,aql[kt],bh);   mma16816(s0,aqh[kt],bl);
                mma16816(s1,aqh[kt],bh+2); mma16816(s1,aql[kt],bh+2); mma16816(s1,aqh[kt],bl+2);
            }
        }

        // ---- online softmax (base 2) ----
        float mxa=-1e30f,mxb=-1e30f;
        #pragma unroll
        for(int nt=0;nt<8;nt++){
            mxa=fmaxf(mxa,fmaxf(sacc[nt][0],sacc[nt][1]));
            mxb=fmaxf(mxb,fmaxf(sacc[nt][2],sacc[nt][3]));
        }
        mxa=fmaxf(mxa,__shfl_xor_sync(0xffffffffu,mxa,1));
        mxa=fmaxf(mxa,__shfl_xor_sync(0xffffffffu,mxa,2));
        mxb=fmaxf(mxb,__shfl_xor_sync(0xffffffffu,mxb,1));
        mxb=fmaxf(mxb,__shfl_xor_sync(0xffffffffu,mxb,2));
        float mna=fmaxf(ma,mxa), mnb=fmaxf(mb,mxb);
        float ala=ex2(ma-mna), alb=ex2(mb-mnb);
        ma=mna; mb=mnb;
        float rsa=0.0f, rsb=0.0f;
        #pragma unroll
        for(int nt=0;nt<8;nt++){
            sacc[nt][0]=ex2(sacc[nt][0]-mna);
            sacc[nt][1]=ex2(sacc[nt][1]-mna);
            sacc[nt][2]=ex2(sacc[nt][2]-mnb);
            sacc[nt][3]=ex2(sacc[nt][3]-mnb);
            rsa+=sacc[nt][0]+sacc[nt][1];
            rsb+=sacc[nt][2]+sacc[nt][3];
        }
        rsa+=__shfl_xor_sync(0xffffffffu,rsa,1);
        rsa+=__shfl_xor_sync(0xffffffffu,rsa,2);
        rsb+=__shfl_xor_sync(0xffffffffu,rsb,1);
        rsb+=__shfl_xor_sync(0xffffffffu,rsb,2);
        la=la*ala+rsa; lb=lb*alb+rsb;
        #pragma unroll
        for(int dt=0;dt<8;dt++){
            oacc[dt][0]*=ala; oacc[dt][1]*=ala;
            oacc[dt][2]*=alb; oacc[dt][3]*=alb;
        }

        // ---- PV per kt: P fp16 2-way; O += PhVh + PlVh + PhVl ----
        #pragma unroll
        for(int kt=0;kt<4;kt++){
            u32 ph[4], pl[4];
            #pragma unroll
            for(int half=0;half<2;half++){
                const int nt=2*kt+half;
                #pragma unroll
                for(int rr=0;rr<2;rr++){
                    float p0=sacc[nt][rr*2], p1=sacc[nt][rr*2+1];
                    __half h0,l0,h1,l1;
                    split2h(p0,h0,l0); split2h(p1,h1,l1);
                    ph[half*2+rr]=packh(h0,h1);
                    pl[half*2+rr]=packh(l0,l1);
                }
            }
            #pragma unroll
            for(int dtp=0;dtp<4;dtp++){
                const int rowB=dtp*16+browB;
                const u32 offV=(u32)(rowB*128)+(u32)((((kt*2+kcB))^(rowB&7))<<4);
                u32 vh[4],vl[4];
                ldmx4(vh,kb+16384+offV);
                ldmx4(vl,kb+24576+offV);
                float* o0=oacc[2*dtp]; float* o1=oacc[2*dtp+1];
                mma16816(o0,ph,vh);   mma16816(o0,pl,vh);   mma16816(o0,ph,vl);
                mma16816(o1,ph,vh+2); mma16816(o1,pl,vh+2); mma16816(o1,ph,vl+2);
            }
        }
        __syncthreads();
    }

    { // epilogue: normalize -> next-stage scaled q planes (fp16 2-way)
        const float inva=1.0f/la, invb=1.0f/lb;
        const int qa=r0+wid*16+(lane>>2), qb=qa+8;
        const size_t basea=(size_t)qa*DIMSZ+h*HD, baseb=(size_t)qb*DIMSZ+h*HD;
        #pragma unroll
        for(int dt=0;dt<8;dt++){
            const int d=dt*8+2*(lane&3);
            float v0=oacc[dt][0]*inva*SCALE_LOG2, v1=oacc[dt][1]*inva*SCALE_LOG2;
            float v2=oacc[dt][2]*invb*SCALE_LOG2, v3=oacc[dt][3]*invb*SCALE_LOG2;
            __half x0,x1,y0,y1;
            split2h(v0,x0,x1); split2h(v1,y0,y1);
            *(u32*)&g_q0[basea+d]=packh(x0,y0);
            *(u32*)&g_q1[basea+d]=packh(x1,y1);
            split2h(v2,x0,x1); split2h(v3,y0,y1);
            *(u32*)&g_q0[baseb+d]=packh(x0,y0);
            *(u32*)&g_q1[baseb+d]=packh(x1,y1);
        }
    }
}

extern "C" void kernel_launch(void* const* d_in, const int* in_sizes, int n_in,
                              void* d_out, int out_size){
    (void)in_sizes;(void)n_in;(void)out_size;
    const float* x=(const float*)d_in[0];
    const float* mem=(const float*)d_in[1];
    const float* Wq=(const float*)d_in[2];
    const float* bq=(const float*)d_in[3];
    const float* Wo=(const float*)d_in[4];
    const float* bo=(const float*)d_in[5];
    float* out=(float*)d_out;

    __half *x0,*x1,*x2,*wq0,*wq1,*wq2,*wo0,*wo1,*q0,*q1;
    cudaGetSymbolAddress((void**)&x0,g_x0);  cudaGetSymbolAddress((void**)&x1,g_x1);
    cudaGetSymbolAddress((void**)&x2,g_x2);
    cudaGetSymbolAddress((void**)&wq0,g_wq0);cudaGetSymbolAddress((void**)&wq1,g_wq1);
    cudaGetSymbolAddress((void**)&wq2,g_wq2);
    cudaGetSymbolAddress((void**)&wo0,g_wo0);cudaGetSymbolAddress((void**)&wo1,g_wo1);
    cudaGetSymbolAddress((void**)&q0,g_q0);  cudaGetSymbolAddress((void**)&q1,g_q1);

    cudaFuncSetAttribute(hopfield_mma_kernel,cudaFuncAttributeMaxDynamicSharedMemorySize,SMEM_AT);
    cudaFuncSetAttribute(linear6_kernel,cudaFuncAttributeMaxDynamicSharedMemorySize,SMEM_L6);
    cudaFuncSetAttribute(linear3_kernel,cudaFuncAttributeMaxDynamicSharedMemorySize,SMEM_L3);

    dim3 lg(DIMSZ/128,BL/128), ag(BL/128,NHEADS);

    mem_split_kernel<<<(MROWS*HD+255)/256,256>>>(mem);
    split3h_kernel<<<(u32)((size_t)BL*DIMSZ/2/256),256>>>(x,x0,x1,x2);
    split3h_kernel<<<DIMSZ*DIMSZ/2/256,256>>>(Wq,wq0,wq1,wq2);
    split2h_kernel<<<DIMSZ*DIMSZ/2/256,256>>>(Wo,wo0,wo1);
    linear6_kernel<<<lg,256,SMEM_L6>>>(x0,x1,x2,wq0,wq1,wq2,bq);
    hopfield_mma_kernel<<<ag,256,SMEM_AT>>>();
    hopfield_mma_kernel<<<ag,256,SMEM_AT>>>();
    linear3_kernel<<<lg,256,SMEM_L3>>>(q0,q1,wo0,wo1,bo,out);
}

// round 15
// speedup vs baseline: 3.7876x; 1.0489x over previous
#include <cuda_runtime.h>
#include <cuda_fp16.h>
#include <cstdint>
#include <cstddef>

#define DIMSZ 1024
#define HD 64
#define NHEADS 16
#define BL 4096
#define MROWS 2048
#define MC 64
#define NCH (MROWS/MC)
#define SCALE_LOG2 23.083120654223414f
#define INV_SCALE  (1.0f/SCALE_LOG2)

typedef uint32_t u32;

__device__ __align__(16) __half g_k0[MROWS*HD], g_k1[MROWS*HD];
__device__ __align__(16) __half g_vT0[HD*MROWS], g_vT1[HD*MROWS];
__device__ __align__(16) __half g_q0[(size_t)BL*DIMSZ], g_q1[(size_t)BL*DIMSZ];
__device__ __align__(16) __half g_x0[(size_t)BL*DIMSZ], g_x1[(size_t)BL*DIMSZ];
__device__ __align__(16) __half g_wq0[DIMSZ*DIMSZ], g_wq1[DIMSZ*DIMSZ];
__device__ __align__(16) __half g_wo0[DIMSZ*DIMSZ], g_wo1[DIMSZ*DIMSZ];

__device__ __forceinline__ float ex2(float x){float r;asm("ex2.approx.f32 %0,%1;":"=f"(r):"f"(x));return r;}
__device__ __forceinline__ u32 smem_u32(const void*p){u32 a;asm("{ .reg .u64 t; cvta.to.shared.u64 t,%1; cvt.u32.u64 %0,t; }":"=r"(a):"l"(p));return a;}
__device__ __forceinline__ u32 packh(__half lo,__half hi){return (u32)__half_as_ushort(lo)|((u32)__half_as_ushort(hi)<<16);}
__device__ __forceinline__ void split2h(float s,__half&a,__half&b){
    a=__float2half_rn(s); b=__float2half_rn(s-__half2float(a));
}
__device__ __forceinline__ void ldmx4(u32* r,u32 a){
    asm volatile("ldmatrix.sync.aligned.m8n8.x4.shared.b16 {%0,%1,%2,%3},[%4];"
        :"=r"(r[0]),"=r"(r[1]),"=r"(r[2]),"=r"(r[3]):"r"(a));
}
__device__ __forceinline__ void mma16816(float* c,const u32* a,const u32* b){
    asm volatile("mma.sync.aligned.m16n8k16.row.col.f32.f16.f16.f32 "
        "{%0,%1,%2,%3},{%4,%5,%6,%7},{%8,%9},{%0,%1,%2,%3};"
        :"+f"(c[0]),"+f"(c[1]),"+f"(c[2]),"+f"(c[3])
        :"r"(a[0]),"r"(a[1]),"r"(a[2]),"r"(a[3]),"r"(b[0]),"r"(b[1]));
}
__device__ __forceinline__ void cpasync16(u32 dst,const void* src){
    asm volatile("cp.async.cg.shared.global [%0],[%1],16;"::"r"(dst),"l"(src));
}
#define CP_COMMIT() asm volatile("cp.async.commit_group;":::"memory")
#define CP_WAIT(n)  asm volatile("cp.async.wait_group %0;"::"n"(n):"memory")

// ---------------- prep ----------------
__global__ void split2h_kernel(const float* __restrict__ src,
                               __half* __restrict__ d0,__half* __restrict__ d1){
    size_t i2=((size_t)blockIdx.x*256+threadIdx.x)*2;
    float2 v=*(const float2*)(src+i2);
    __half x0,x1,y0,y1;
    split2h(v.x,x0,x1); split2h(v.y,y0,y1);
    *(u32*)&d0[i2]=packh(x0,y0);
    *(u32*)&d1[i2]=packh(x1,y1);
}
__global__ void mem_split_kernel(const float* __restrict__ mem){
    int i=blockIdx.x*256+threadIdx.x;
    if(i>=MROWS*HD) return;
    int m=i>>6, d=i&63;
    __half b0,b1; split2h(mem[i],b0,b1);
    g_k0[i]=b0; g_k1[i]=b1;
    g_vT0[d*MROWS+m]=b0; g_vT1[d*MROWS+m]=b1;
}

// ---------------- linear: 2x2 fp16 planes, 4 products ----------------
// mode 0 (Wq): write split2h((acc+bias)*SCALE) -> g_q planes
// mode 1 (Wo): write acc*INV_SCALE+bias fp32 -> outp
#define SMEM_L 65536
__global__ void __launch_bounds__(256,2)
linear4_kernel(const __half* __restrict__ a0,const __half* __restrict__ a1,
               const __half* __restrict__ w0,const __half* __restrict__ w1,
               const float* __restrict__ bias,float* __restrict__ outp,int mode){
    extern __shared__ char smc[];
    const u32 sb=smem_u32(smc);
    const int tid=threadIdx.x, wid=tid>>5, lane=tid&31;
    const int i0=blockIdx.y*128, j0=blockIdx.x*128;

    float sacc[16][4];
    #pragma unroll
    for(int n=0;n<16;n++){sacc[n][0]=0;sacc[n][1]=0;sacc[n][2]=0;sacc[n][3]=0;}

    const int arow=wid*16+(lane&15);
    const u32 arow128=(u32)(arow*128);
    const int arx=arow&7, acs=lane>>4;
    const int browB=((lane>>4)<<3)+(lane&7);
    const int kcB=(lane>>3)&1;

    for(int kc=0;kc<16;kc++){
        __syncthreads();
        {
            const __half* ga[2]={a0,a1};
            const __half* gw[2]={w0,w1};
            #pragma unroll
            for(int s=0;s<2;s++)
                #pragma unroll
                for(int j=0;j<4;j++){
                    int idx=tid+256*j, row=idx>>3, cc=idx&7;
                    u32 so=(u32)(row*128+((cc^(row&7))<<4));
                    *(uint4*)(smc+s*16384+so)
                        =*(const uint4*)(ga[s]+(size_t)(i0+row)*DIMSZ+kc*64+cc*8);
                    *(uint4*)(smc+32768+s*16384+so)
                        =*(const uint4*)(gw[s]+(size_t)(j0+row)*DIMSZ+kc*64+cc*8);
                }
        }
        __syncthreads();
        #pragma unroll
        for(int kt=0;kt<4;kt++){
            u32 aq[2][4];
            const u32 ca=arow128+(u32)(((kt*2+acs)^arx)<<4);
            ldmx4(aq[0],sb+ca);
            ldmx4(aq[1],sb+16384+ca);
            #pragma unroll
            for(int ntp=0;ntp<8;ntp++){
                const int rowB=ntp*16+browB;
                const u32 offB=(u32)(rowB*128)+(u32)(((kt*2+kcB)^(rowB&7))<<4);
                float* s0=sacc[2*ntp]; float* s1=sacc[2*ntp+1];
                u32 bh[4],bl[4];
                ldmx4(bh,sb+32768+offB);
                ldmx4(bl,sb+49152+offB);
                mma16816(s0,aq[0],bh);   mma16816(s0,aq[1],bh);
                mma16816(s0,aq[0],bl);   mma16816(s0,aq[1],bl);
                mma16816(s1,aq[0],bh+2); mma16816(s1,aq[1],bh+2);
                mma16816(s1,aq[0],bl+2); mma16816(s1,aq[1],bl+2);
            }
        }
    }

    const int ra=i0+wid*16+(lane>>2), rb=ra+8;
    #pragma unroll
    for(int nt=0;nt<16;nt++){
        const int j=j0+nt*8+2*(lane&3);
        float2 bv=*(const float2*)(bias+j);
        if(mode==0){
            float v0=(sacc[nt][0]+bv.x)*SCALE_LOG2;
            float v1=(sacc[nt][1]+bv.y)*SCALE_LOG2;
            float v2=(sacc[nt][2]+bv.x)*SCALE_LOG2;
            float v3=(sacc[nt][3]+bv.y)*SCALE_LOG2;
            __half p0,p1,q0,q1;
            split2h(v0,p0,p1); split2h(v1,q0,q1);
            *(u32*)&g_q0[(size_t)ra*DIMSZ+j]=packh(p0,q0);
            *(u32*)&g_q1[(size_t)ra*DIMSZ+j]=packh(p1,q1);
            split2h(v2,p0,p1); split2h(v3,q0,q1);
            *(u32*)&g_q0[(size_t)rb*DIMSZ+j]=packh(p0,q0);
            *(u32*)&g_q1[(size_t)rb*DIMSZ+j]=packh(p1,q1);
        }else{
            *(float2*)(outp+(size_t)ra*DIMSZ+j)
                =make_float2(sacc[nt][0]*INV_SCALE+bv.x,sacc[nt][1]*INV_SCALE+bv.y);
            *(float2*)(outp+(size_t)rb*DIMSZ+j)
                =make_float2(sacc[nt][2]*INV_SCALE+bv.x,sacc[nt][3]*INV_SCALE+bv.y);
        }
    }
}

// ---------------- fused double-iteration attention ----------------
#define BUFO(b) ((b)*32768)
#define SMEM_AT 65536

__global__ void __launch_bounds__(256,2)
hopfield2_kernel(){
    extern __shared__ char smc[];
    const u32 sb=smem_u32(smc);
    const int tid=threadIdx.x, wid=tid>>5, lane=tid&31;
    const int h=blockIdx.y, r0=blockIdx.x*128;

    const int arow=wid*16+(lane&15);
    const u32 arow128=(u32)(arow*128);
    const int arx=arow&7, acs=lane>>4;
    const int browB=((lane>>4)<<3)+(lane&7);
    const int kcB=(lane>>3)&1;

    // ---- stage q0,q1 once; fragments live in registers across both iters ----
    u32 aqh[4][4], aql[4][4];
    #pragma unroll
    for(int j=0;j<4;j++){
        int idx=tid+256*j, row=idx>>3, c=idx&7;
        *(uint4*)(smc+row*128+((c^(row&7))<<4))
            =*(const uint4*)(g_q0+(size_t)(r0+row)*DIMSZ+h*HD+c*8);
    }
    __syncthreads();
    #pragma unroll
    for(int kt=0;kt<4;kt++) ldmx4(aqh[kt],sb+arow128+(u32)(((kt*2+acs)^arx)<<4));
    __syncthreads();
    #pragma unroll
    for(int j=0;j<4;j++){
        int idx=tid+256*j, row=idx>>3, c=idx&7;
        *(uint4*)(smc+row*128+((c^(row&7))<<4))
            =*(const uint4*)(g_q1+(size_t)(r0+row)*DIMSZ+h*HD+c*8);
    }
    __syncthreads();
    #pragma unroll
    for(int kt=0;kt<4;kt++) ldmx4(aql[kt],sb+arow128+(u32)(((kt*2+acs)^arx)<<4));
    __syncthreads();

    auto issue=[&](int c,u32 bofs){
        const __half* gk[2]={g_k0,g_k1};
        #pragma unroll
        for(int s=0;s<2;s++)
            #pragma unroll
            for(int j=0;j<2;j++){
                int idx=tid+256*j, row=idx>>3, cc=idx&7;
                cpasync16(sb+bofs+(u32)(s*8192+row*128+((cc^(row&7))<<4)),
                          gk[s]+(size_t)(c*MC+row)*HD+cc*8);
            }
        const __half* gv[2]={g_vT0,g_vT1};
        #pragma unroll
        for(int s=0;s<2;s++)
            #pragma unroll
            for(int j=0;j<2;j++){
                int idx=tid+256*j, row=idx>>3, cc=idx&7;
                cpasync16(sb+bofs+(u32)(16384+s*8192+row*128+((cc^(row&7))<<4)),
                          gv[s]+(size_t)row*MROWS+c*MC+cc*8);
            }
    };

    float oacc[8][4];
    float ma,mb,la,lb;

    for(int it=0;it<2;it++){
        ma=-1e30f; mb=-1e30f; la=0.0f; lb=0.0f;
        #pragma unroll
        for(int i=0;i<8;i++){oacc[i][0]=0;oacc[i][1]=0;oacc[i][2]=0;oacc[i][3]=0;}

        issue(0,BUFO(0));
        CP_COMMIT();

        for(int c=0;c<NCH;c++){
            if(c+1<NCH){ issue(c+1,BUFO((c+1)&1)); CP_COMMIT(); CP_WAIT(1); }
            else CP_WAIT(0);
            __syncthreads();

            const u32 kb=sb+BUFO(c&1);

            // ---- S = Q@K^T: hh + lh + hl ----
            float sacc[8][4];
            #pragma unroll
            for(int i=0;i<8;i++){sacc[i][0]=0;sacc[i][1]=0;sacc[i][2]=0;sacc[i][3]=0;}
            #pragma unroll
            for(int kt=0;kt<4;kt++){
                #pragma unroll
                for(int ntp=0;ntp<4;ntp++){
                    const int rowB=ntp*16+browB;
                    const u32 offB=(u32)(rowB*128)+(u32)((((kt*2+kcB))^(rowB&7))<<4);
                    u32 bh[4],bl[4];
                    ldmx4(bh,kb+offB);
                    ldmx4(bl,kb+8192+offB);
                    float* s0=sacc[2*ntp]; float* s1=sacc[2*ntp+1];
                    mma16816(s0,aqh[kt],bh);   mma16816(s0,aql[kt],bh);   mma16816(s0,aqh[kt],bl);
                    mma16816(s1,aqh[kt],bh+2); mma16816(s1,aql[kt],bh+2); mma16816(s1,aqh[kt],bl+2);
                }
            }

            // ---- online softmax (base 2) ----
            float mxa=-1e30f,mxb=-1e30f;
            #pragma unroll
            for(int nt=0;nt<8;nt++){
                mxa=fmaxf(mxa,fmaxf(sacc[nt][0],sacc[nt][1]));
                mxb=fmaxf(mxb,fmaxf(sacc[nt][2],sacc[nt][3]));
            }
            mxa=fmaxf(mxa,__shfl_xor_sync(0xffffffffu,mxa,1));
            mxa=fmaxf(mxa,__shfl_xor_sync(0xffffffffu,mxa,2));
            mxb=fmaxf(mxb,__shfl_xor_sync(0xffffffffu,mxb,1));
            mxb=fmaxf(mxb,__shfl_xor_sync(0xffffffffu,mxb,2));
            float mna=fmaxf(ma,mxa), mnb=fmaxf(mb,mxb);
            float ala=ex2(ma-mna), alb=ex2(mb-mnb);
            ma=mna; mb=mnb;
            float rsa=0.0f, rsb=0.0f;
            #pragma unroll
            for(int nt=0;nt<8;nt++){
                sacc[nt][0]=ex2(sacc[nt][0]-mna);
                sacc[nt][1]=ex2(sacc[nt][1]-mna);
                sacc[nt][2]=ex2(sacc[nt][2]-mnb);
                sacc[nt][3]=ex2(sacc[nt][3]-mnb);
                rsa+=sacc[nt][0]+sacc[nt][1];
                rsb+=sacc[nt][2]+sacc[nt][3];
            }
            rsa+=__shfl_xor_sync(0xffffffffu,rsa,1);
            rsa+=__shfl_xor_sync(0xffffffffu,rsa,2);
            rsb+=__shfl_xor_sync(0xffffffffu,rsb,1);
            rsb+=__shfl_xor_sync(0xffffffffu,rsb,2);
            la=la*ala+rsa; lb=lb*alb+rsb;
            #pragma unroll
            for(int dt=0;dt<8;dt++){
                oacc[dt][0]*=ala; oacc[dt][1]*=ala;
                oacc[dt][2]*=alb; oacc[dt][3]*=alb;
            }

            // ---- PV per kt: O += PhVh + PlVh + PhVl ----
            #pragma unroll
            for(int kt=0;kt<4;kt++){
                u32 ph[4], pl[4];
                #pragma unroll
                for(int half=0;half<2;half++){
                    const int nt=2*kt+half;
                    #pragma unroll
                    for(int rr=0;rr<2;rr++){
                        float p0=sacc[nt][rr*2], p1=sacc[nt][rr*2+1];
                        __half h0,l0,h1,l1;
                        split2h(p0,h0,l0); split2h(p1,h1,l1);
                        ph[half*2+rr]=packh(h0,h1);
                        pl[half*2+rr]=packh(l0,l1);
                    }
                }
                #pragma unroll
                for(int dtp=0;dtp<4;dtp++){
                    const int rowB=dtp*16+browB;
                    const u32 offV=(u32)(rowB*128)+(u32)((((kt*2+kcB))^(rowB&7))<<4);
                    u32 vh[4],vl[4];
                    ldmx4(vh,kb+16384+offV);
                    ldmx4(vl,kb+24576+offV);
                    float* o0=oacc[2*dtp]; float* o1=oacc[2*dtp+1];
                    mma16816(o0,ph,vh);   mma16816(o0,pl,vh);   mma16816(o0,ph,vl);
                    mma16816(o1,ph,vh+2); mma16816(o1,pl,vh+2); mma16816(o1,ph,vl+2);
                }
            }
            __syncthreads();
        }

        if(it==0){
            // ---- convert O -> next-iteration Q fragments, in registers ----
            const float sa=SCALE_LOG2/la, sb2=SCALE_LOG2/lb;
            #pragma unroll
            for(int kt=0;kt<4;kt++){
                #pragma unroll
                for(int half=0;half<2;half++){
                    const int nt=2*kt+half;
                    #pragma unroll
                    for(int rr=0;rr<2;rr++){
                        const float sc=(rr==0)?sa:sb2;
                        float v0=oacc[nt][rr*2]*sc, v1=oacc[nt][rr*2+1]*sc;
                        __half h0,l0,h1,l1;
                        split2h(v0,h0,l0); split2h(v1,h1,l1);
                        aqh[kt][half*2+rr]=packh(h0,h1);
                        aql[kt][half*2+rr]=packh(l0,l1);
                    }
                }
            }
        }
    }

    { // final epilogue: scaled q planes for linear3 (Wo divides SCALE out)
        const float sa=SCALE_LOG2/la, sb2=SCALE_LOG2/lb;
        const int qa=r0+wid*16+(lane>>2), qb=qa+8;
        const size_t basea=(size_t)qa*DIMSZ+h*HD, baseb=(size_t)qb*DIMSZ+h*HD;
        #pragma unroll
        for(int dt=0;dt<8;dt++){
            const int d=dt*8+2*(lane&3);
            float v0=oacc[dt][0]*sa, v1=oacc[dt][1]*sa;
            float v2=oacc[dt][2]*sb2, v3=oacc[dt][3]*sb2;
            __half x0,x1,y0,y1;
            split2h(v0,x0,x1); split2h(v1,y0,y1);
            *(u32*)&g_q0[basea+d]=packh(x0,y0);
            *(u32*)&g_q1[basea+d]=packh(x1,y1);
            split2h(v2,x0,x1); split2h(v3,y0,y1);
            *(u32*)&g_q0[baseb+d]=packh(x0,y0);
            *(u32*)&g_q1[baseb+d]=packh(x1,y1);
        }
    }
}

extern "C" void kernel_launch(void* const* d_in, const int* in_sizes, int n_in,
                              void* d_out, int out_size){
    (void)in_sizes;(void)n_in;(void)out_size;
    const float* x=(const float*)d_in[0];
    const float* mem=(const float*)d_in[1];
    const float* Wq=(const float*)d_in[2];
    const float* bq=(const float*)d_in[3];
    const float* Wo=(const float*)d_in[4];
    const float* bo=(const float*)d_in[5];
    float* out=(float*)d_out;

    __half *x0,*x1,*wq0,*wq1,*wo0,*wo1,*q0,*q1;
    cudaGetSymbolAddress((void**)&x0,g_x0);  cudaGetSymbolAddress((void**)&x1,g_x1);
    cudaGetSymbolAddress((void**)&wq0,g_wq0);cudaGetSymbolAddress((void**)&wq1,g_wq1);
    cudaGetSymbolAddress((void**)&wo0,g_wo0);cudaGetSymbolAddress((void**)&wo1,g_wo1);
    cudaGetSymbolAddress((void**)&q0,g_q0);  cudaGetSymbolAddress((void**)&q1,g_q1);

    cudaFuncSetAttribute(hopfield2_kernel,cudaFuncAttributeMaxDynamicSharedMemorySize,SMEM_AT);
    cudaFuncSetAttribute(linear4_kernel,cudaFuncAttributeMaxDynamicSharedMemorySize,SMEM_L);

    dim3 lg(DIMSZ/128,BL/128), ag(BL/128,NHEADS);

    mem_split_kernel<<<(MROWS*HD+255)/256,256>>>(mem);
    split2h_kernel<<<(u32)((size_t)BL*DIMSZ/2/256),256>>>(x,x0,x1);
    split2h_kernel<<<DIMSZ*DIMSZ/2/256,256>>>(Wq,wq0,wq1);
    split2h_kernel<<<DIMSZ*DIMSZ/2/256,256>>>(Wo,wo0,wo1);
    linear4_kernel<<<lg,256,SMEM_L>>>(x0,x1,wq0,wq1,bq,nullptr,0);
    hopfield2_kernel<<<ag,256,SMEM_AT>>>();
    linear4_kernel<<<lg,256,SMEM_L>>>(q0,q1,wo0,wo1,bo,out,1);
}